// round 13
// baseline (speedup 1.0000x reference)
#include <cuda_runtime.h>
#include <cuda_fp16.h>
#include <math.h>
#include <stdint.h>

#define Nn   16
#define Cc   256
#define C1c  128
#define HWc  3136
#define EPSf 1e-5f
#define PBI  25
#define NPB  (Nn*PBI)
#define SF   (Cc*HWc)
#define SH   (C1c*HWc)

// ---------------- scratch (device globals; no allocations) ----------------
__device__ float g_att[Nn*C1c];
__device__ float g_a  [Nn*C1c*3];

__device__ uint4 g_ybh4[(Nn*Cc *HWc + 256) / 8];
__device__ uint4 g_ybl4[(Nn*Cc *HWc + 256) / 8];
__device__ uint4 g_cbh4[(Nn*C1c*HWc + 256) / 8];
__device__ uint4 g_cbl4[(Nn*C1c*HWc + 256) / 8];
__device__ uint4 g_u1h4[(Nn*C1c*HWc + 256) / 8];
__device__ uint4 g_x2h4[(Nn*C1c*HWc + 256) / 8];
__device__ uint4 g_x2w4[(Nn*C1c*HWc + 256) / 8];
// prepped weights (fp16): 6 slots x 8 chunks x [128 n][40 halves]
__device__ uint4 g_wf4[6 * 40960 / 8];

__device__ __forceinline__ float gelu_f(float x) {
    return 0.5f * x * (1.0f + erff(x * 0.7071067811865476f));
}
__device__ __forceinline__ uint32_t smem_to_u32(const void* p) {
    uint32_t a;
    asm("{ .reg .u64 t; cvta.to.shared.u64 t, %1; cvt.u32.u64 %0, t; }" : "=r"(a) : "l"(p));
    return a;
}
__device__ __forceinline__ void split_fp2(float x0, float x1, uint32_t& hi, uint32_t& lo) {
    const __half h0 = __float2half_rn(x0);
    const __half h1 = __float2half_rn(x1);
    const __half l0 = __float2half_rn(x0 - __half2float(h0));
    const __half l1 = __float2half_rn(x1 - __half2float(h1));
    hi = (uint32_t)__half_as_ushort(h0) | ((uint32_t)__half_as_ushort(h1) << 16);
    lo = (uint32_t)__half_as_ushort(l0) | ((uint32_t)__half_as_ushort(l1) << 16);
}
__device__ __forceinline__ uint32_t pack_fp2(float x0, float x1) {
    const __half h0 = __float2half_rn(x0);
    const __half h1 = __float2half_rn(x1);
    return (uint32_t)__half_as_ushort(h0) | ((uint32_t)__half_as_ushort(h1) << 16);
}
__device__ __forceinline__ void ldsm4(uint32_t (&r)[4], uint32_t addr) {
    asm volatile("ldmatrix.sync.aligned.m8n8.x4.shared.b16 {%0,%1,%2,%3}, [%4];"
        : "=r"(r[0]), "=r"(r[1]), "=r"(r[2]), "=r"(r[3]) : "r"(addr));
}
__device__ __forceinline__ void ldsm4t(uint32_t (&r)[4], uint32_t addr) {
    asm volatile("ldmatrix.sync.aligned.m8n8.x4.trans.shared.b16 {%0,%1,%2,%3}, [%4];"
        : "=r"(r[0]), "=r"(r[1]), "=r"(r[2]), "=r"(r[3]) : "r"(addr));
}
__device__ __forceinline__ void mma16816(float (&c)[4], const uint32_t (&a)[4], uint32_t b0, uint32_t b1) {
    asm volatile("mma.sync.aligned.m16n8k16.row.col.f32.f16.f16.f32 "
        "{%0,%1,%2,%3}, {%4,%5,%6,%7}, {%8,%9}, {%0,%1,%2,%3};"
        : "+f"(c[0]), "+f"(c[1]), "+f"(c[2]), "+f"(c[3])
        : "r"(a[0]), "r"(a[1]), "r"(a[2]), "r"(a[3]), "r"(b0), "r"(b1));
}
#define CP16(dst, src) asm volatile("cp.async.cg.shared.global [%0], [%1], 16;" :: "r"(dst), "l"(src))
#define CP_COMMIT()    asm volatile("cp.async.commit_group;" ::: "memory")

// ---------------------------------------------------------------------------
// Weight prep (unchanged).
// ---------------------------------------------------------------------------
__global__ __launch_bounds__(256)
void wprep_k(const float* __restrict__ mlp_w, const float* __restrict__ fuse_h,
             const float* __restrict__ fuse_w, const float* __restrict__ fout_w)
{
    const int slot = blockIdx.x, kc = blockIdx.y, tid = threadIdx.x;
    const float* W; int o0;
    switch (slot) {
        case 0: W = mlp_w;  o0 = 0;   break;
        case 1: W = mlp_w;  o0 = 128; break;
        case 2: W = fuse_h; o0 = 0;   break;
        case 3: W = fuse_w; o0 = 0;   break;
        case 4: W = fout_w; o0 = 0;   break;
        default:W = fout_w; o0 = 128; break;
    }
    const int n = tid >> 1;
    const int kh = (tid & 1) * 16;
    const float* src = W + (long)(o0 + n) * 256 + kc * 32 + kh;
    uint32_t hp[8];
#pragma unroll
    for (int j = 0; j < 8; j++) {
        const float2 v = *reinterpret_cast<const float2*>(src + 2 * j);
        hp[j] = pack_fp2(v.x, v.y);
    }
    __half* dh = (__half*)g_wf4 + (long)slot * 40960 + kc * 5120 + n * 40 + kh;
    *reinterpret_cast<uint4*>(dh)     = *reinterpret_cast<uint4*>(&hp[0]);
    *reinterpret_cast<uint4*>(dh + 8) = *reinterpret_cast<uint4*>(&hp[4]);
    if (tid < 128) {
        const uint4 z = {0, 0, 0, 0};
        *reinterpret_cast<uint4*>((__half*)g_wf4 + (long)slot * 40960 + kc * 5120 + tid * 40 + 32) = z;
    }
}

// ---------------------------------------------------------------------------
// Generic GEMM. APATH: 1 = fp32 convert 2-term (GEMM1, x input);
//                2 = GEMM4: chunks 0-3 u1 fp16 single (1-term),
//                    chunks 4-7 comb -> fp16 single (1-term).
// EPI: 0 none; 1 +bias,BN,gelu,+pos(o<128). OUT: 0 fp32; 2 fp16 hi/lo.
// ---------------------------------------------------------------------------
#define STG 27648
#define ALB 8704
#define BHB 17408
#define SMEM_GEMM 67584

template<int APATH, int EPI, int OUT>
__global__ __launch_bounds__(256, 2)
void tc_gemm(const __half* __restrict__ wf,
             const __half* __restrict__ s1h, int str1,
             const __half* __restrict__ s2h, const __half* __restrict__ s2l, int str2,
             const float* __restrict__ xin, int strX,
             float* __restrict__ out, int strO,
             __half* __restrict__ obh, __half* __restrict__ obl, int strOB,
             const float* __restrict__ e_bias,
             const float* __restrict__ e_g, const float* __restrict__ e_b,
             const float* __restrict__ e_m, const float* __restrict__ e_v,
             const float* __restrict__ e_pos,
             const __half* __restrict__ cH, const __half* __restrict__ cW,
             const float* __restrict__ cA)
{
    extern __shared__ __align__(16) char smc[];
    const uint32_t sm_sa = smem_to_u32(smc);

    const int tid = threadIdx.x;
    const int wid = tid >> 5;
    const int lane = tid & 31;
    const int o0 = blockIdx.x * 128;
    const int nimg = blockIdx.y / PBI;
    const int pix0 = (blockIdx.y % PBI) * 128;
    const int warp_m = (wid & 3) * 32;
    const int warp_n = (wid >> 2) * 64;

    const __half* wfB = wf + (long)blockIdx.x * 40960;

    const int pix2 = tid & 63;
    const int rgrp = tid >> 6;
    int p0 = pix0 + 2 * pix2;
    if (p0 > HWc - 2) p0 = HWc - 2;

    auto issue = [&](int kc, int buf) {
        const uint32_t base = sm_sa + buf * STG;
        char* bp = smc + buf * STG;
        if (APATH == 1) {
            const float* src = xin + (long)nimg * strX + p0;
#pragma unroll
            for (int j = 0; j < 8; j++) {
                const int r = rgrp + 4 * j;
                const float2 v = *reinterpret_cast<const float2*>(src + (long)(kc * 32 + r) * HWc);
                uint32_t hi, lo;
                split_fp2(v.x, v.y, hi, lo);
                *reinterpret_cast<uint32_t*>(bp + r * 272 + pix2 * 4) = hi;
                *reinterpret_cast<uint32_t*>(bp + ALB + r * 272 + pix2 * 4) = lo;
            }
        } else if (kc < 4) {
            // u1 fp16 single
            const long chb = (long)nimg * str1 + (long)(kc * 32) * HWc + pix0;
#pragma unroll
            for (int it = 0; it < 2; it++) {
                const int idx = tid + it * 256;
                const int row = idx >> 4, seg = idx & 15;
                const char* gh = (const char*)(s1h + chb + (long)row * HWc) + seg * 16;
                CP16(base + row * 272 + seg * 16, gh);
            }
        } else {
            // comb = a0*x2h + a1*x2w + a2*(y2h + y2l) -> fp16 single
            const long ib = (long)nimg * SH + p0;
            const __half* pH = cH + ib;
            const __half* pW = cW + ib;
            const __half* pXh = s2h + (long)nimg * str2 + p0;
            const __half* pXl = s2l + (long)nimg * str2 + p0;
            const float* aB = cA + nimg * 384;
#pragma unroll
            for (int j = 0; j < 8; j++) {
                const int r = rgrp + 4 * j;
                const int cc = (kc - 4) * 32 + r;
                const float a0 = aB[cc * 3], a1 = aB[cc * 3 + 1], a2 = aB[cc * 3 + 2];
                const __half2 vh2 = *reinterpret_cast<const __half2*>(pH + (long)cc * HWc);
                const __half2 vw2 = *reinterpret_cast<const __half2*>(pW + (long)cc * HWc);
                const __half2 xh2 = *reinterpret_cast<const __half2*>(pXh + (long)cc * HWc);
                const __half2 xl2 = *reinterpret_cast<const __half2*>(pXl + (long)cc * HWc);
                float2 v;
                v.x = a0 * __half2float(vh2.x) + a1 * __half2float(vw2.x)
                    + a2 * (__half2float(xh2.x) + __half2float(xl2.x));
                v.y = a0 * __half2float(vh2.y) + a1 * __half2float(vw2.y)
                    + a2 * (__half2float(xh2.y) + __half2float(xl2.y));
                *reinterpret_cast<uint32_t*>(bp + r * 272 + pix2 * 4) = pack_fp2(v.x, v.y);
            }
        }
        const char* wsrc = (const char*)(wfB + kc * 5120);
#pragma unroll
        for (int it = 0; it < 3; it++) {
            const int i = tid + it * 256;
            if (i < 640) CP16(base + BHB + i * 16, wsrc + i * 16);
        }
    };

    const int a_kr = (lane & 7) + ((lane & 16) >> 1);
    const int a_mc = (lane & 8);
    const int b_nr = (lane & 7) + ((lane & 16) >> 1);
    const int b_kc = (lane & 8);

    float acc[2][8][4];
#pragma unroll
    for (int mt = 0; mt < 2; mt++)
#pragma unroll
        for (int nf = 0; nf < 8; nf++)
#pragma unroll
            for (int j = 0; j < 4; j++) acc[mt][nf][j] = 0.f;

    issue(0, 0);
    CP_COMMIT();

#pragma unroll 1
    for (int kc = 0; kc < 8; kc++) {
        if (kc < 7) { issue(kc + 1, (kc + 1) & 1); CP_COMMIT(); }
        if (kc < 7) asm volatile("cp.async.wait_group 1;" ::: "memory");
        else        asm volatile("cp.async.wait_group 0;" ::: "memory");
        __syncthreads();

        const uint32_t base = sm_sa + (kc & 1) * STG;
#pragma unroll
        for (int ks = 0; ks < 2; ks++) {
            const int k0 = ks * 16;
            uint32_t ah[2][4], al[2][4];
#pragma unroll
            for (int half = 0; half < 2; half++) {
                const uint32_t ea = (uint32_t)((k0 + a_kr) * 136 + warp_m + half * 16 + a_mc) * 2;
                ldsm4t(ah[half], base + ea);
                if (APATH == 1) ldsm4t(al[half], base + ALB + ea);
            }
#pragma unroll
            for (int ng = 0; ng < 4; ng++) {
                const uint32_t eb = (uint32_t)((warp_n + ng * 16 + b_nr) * 40 + k0 + b_kc) * 2;
                uint32_t th[4];
                ldsm4(th, base + BHB + eb);
#pragma unroll
                for (int mt = 0; mt < 2; mt++) {
                    mma16816(acc[mt][2 * ng],     ah[mt], th[0], th[1]);
                    mma16816(acc[mt][2 * ng + 1], ah[mt], th[2], th[3]);
                    if (APATH == 1) {
                        mma16816(acc[mt][2 * ng],     al[mt], th[0], th[1]);
                        mma16816(acc[mt][2 * ng + 1], al[mt], th[2], th[3]);
                    }
                }
            }
        }
        __syncthreads();
    }

    // ---- epilogue ----
    float* O = reinterpret_cast<float*>(smc);
#pragma unroll
    for (int mt = 0; mt < 2; mt++)
#pragma unroll
        for (int nf = 0; nf < 8; nf++) {
            const int n = warp_n + nf * 8 + (lane & 3) * 2;
            const int m = warp_m + mt * 16 + (lane >> 2);
            O[n * 132 + m]           = acc[mt][nf][0];
            O[(n + 1) * 132 + m]     = acc[mt][nf][1];
            O[n * 132 + m + 8]       = acc[mt][nf][2];
            O[(n + 1) * 132 + m + 8] = acc[mt][nf][3];
        }
    __syncthreads();

    {
        const int m0 = lane * 4;
        const int hw0 = pix0 + m0;
        const bool pvalid = (hw0 < HWc);
        int rel[4] = {0, 0, 0, 0};
        if (pvalid && EPI != 0) {
#pragma unroll
            for (int j = 0; j < 4; j++) {
                const int hwj = hw0 + j;
                const int h = hwj / 56;
                rel[j] = (hwj - h * 56) - h + 56;
            }
        }
        if (pvalid) {
#pragma unroll
            for (int r = 0; r < 16; r++) {
                const int n = wid * 16 + r;
                const int o = o0 + n;
                const float4 v = *reinterpret_cast<const float4*>(&O[n * 132 + m0]);
                float vv[4] = {v.x, v.y, v.z, v.w};
                if (EPI == 1) {
                    const float s = __ldg(&e_g[o]) * rsqrtf(__ldg(&e_v[o]) + EPSf);
                    const float t = __ldg(&e_b[o]) - __ldg(&e_m[o]) * s;
                    const float bb = __ldg(&e_bias[o]);
#pragma unroll
                    for (int j = 0; j < 4; j++) {
                        float u = gelu_f((vv[j] + bb) * s + t);
                        if (o < 128) u += __ldg(&e_pos[rel[j] * 128 + o]);
                        vv[j] = u;
                    }
                }
                if (OUT != 2) {
                    float4 ov;
                    ov.x = vv[0]; ov.y = vv[1]; ov.z = vv[2]; ov.w = vv[3];
                    *reinterpret_cast<float4*>(&out[(long)nimg * strO + (long)o * HWc + hw0]) = ov;
                }
                if (OUT != 0) {
                    uint32_t h0, l0, h1, l1;
                    split_fp2(vv[0], vv[1], h0, l0);
                    split_fp2(vv[2], vv[3], h1, l1);
                    const long eoff = (long)nimg * strOB + (long)o * HWc + hw0;
                    *reinterpret_cast<uint2*>(obh + eoff) = make_uint2(h0, h1);
                    *reinterpret_cast<uint2*>(obl + eoff) = make_uint2(l0, l1);
                }
            }
        }
    }
}

// ---------------------------------------------------------------------------
// Fused GEMM2+GEMM3 (unchanged except u1 written fp16 single).
// ---------------------------------------------------------------------------
#define T_OFF 55296
#define SMEM_G23 90112

__global__ __launch_bounds__(256, 2)
void tc_g23(const __half* __restrict__ wf2, const __half* __restrict__ wf3,
            const __half* __restrict__ s1h, const __half* __restrict__ s1l,
            const __half* __restrict__ yh, const __half* __restrict__ yl,
            __half* __restrict__ obh,
            const float* __restrict__ e_g, const float* __restrict__ e_b,
            const float* __restrict__ e_m, const float* __restrict__ e_v,
            const float* __restrict__ e_pos)
{
    extern __shared__ __align__(16) char smc[];
    const uint32_t sm_sa = smem_to_u32(smc);

    const int tid = threadIdx.x;
    const int wid = tid >> 5;
    const int lane = tid & 31;
    const int nimg = blockIdx.y / PBI;
    const int pix0 = (blockIdx.y % PBI) * 128;
    const int warp_m = (wid & 3) * 32;
    const int warp_n = (wid >> 2) * 64;

    const int a_kr = (lane & 7) + ((lane & 16) >> 1);
    const int a_mc = (lane & 8);
    const int b_nr = (lane & 7) + ((lane & 16) >> 1);
    const int b_kc = (lane & 8);

    auto stageA = [&](const __half* sh, const __half* sl, int str, int c0, uint32_t base) {
        const long chb = (long)nimg * str + (long)c0 * HWc + pix0;
#pragma unroll
        for (int it = 0; it < 2; it++) {
            const int idx = tid + it * 256;
            const int row = idx >> 4, seg = idx & 15;
            const char* gh = (const char*)(sh + chb + (long)row * HWc) + seg * 16;
            const char* gl = (const char*)(sl + chb + (long)row * HWc) + seg * 16;
            CP16(base + row * 272 + seg * 16, gh);
            CP16(base + ALB + row * 272 + seg * 16, gl);
        }
    };
    auto stageB = [&](const __half* wf, int kc, uint32_t base) {
        const char* wsrc = (const char*)(wf + kc * 5120);
#pragma unroll
        for (int it = 0; it < 3; it++) {
            const int i = tid + it * 256;
            if (i < 640) CP16(base + BHB + i * 16, wsrc + i * 16);
        }
    };

    float acc[2][8][4];
#pragma unroll
    for (int mt = 0; mt < 2; mt++)
#pragma unroll
        for (int nf = 0; nf < 8; nf++)
#pragma unroll
            for (int j = 0; j < 4; j++) acc[mt][nf][j] = 0.f;

    // =================== phase 1: t1 = concat[cat, y1] @ fuse_h ==============
    auto issue1 = [&](int kc, int buf) {
        const uint32_t base = sm_sa + buf * STG;
        if (kc < 4) stageA(s1h, s1l, SH, kc * 32, base);
        else        stageA(yh,  yl,  SF, (kc - 4) * 32, base);
        stageB(wf2, kc, base);
    };

    issue1(0, 0);
    CP_COMMIT();

#pragma unroll 1
    for (int kc = 0; kc < 8; kc++) {
        if (kc < 7) { issue1(kc + 1, (kc + 1) & 1); CP_COMMIT(); }
        if (kc < 7) asm volatile("cp.async.wait_group 1;" ::: "memory");
        else        asm volatile("cp.async.wait_group 0;" ::: "memory");
        __syncthreads();

        const uint32_t base = sm_sa + (kc & 1) * STG;
#pragma unroll
        for (int ks = 0; ks < 2; ks++) {
            const int k0 = ks * 16;
            uint32_t ah[2][4], al[2][4];
#pragma unroll
            for (int half = 0; half < 2; half++) {
                const uint32_t ea = (uint32_t)((k0 + a_kr) * 136 + warp_m + half * 16 + a_mc) * 2;
                ldsm4t(ah[half], base + ea);
                ldsm4t(al[half], base + ALB + ea);
            }
#pragma unroll
            for (int ng = 0; ng < 4; ng++) {
                const uint32_t eb = (uint32_t)((warp_n + ng * 16 + b_nr) * 40 + k0 + b_kc) * 2;
                uint32_t th[4];
                ldsm4(th, base + BHB + eb);
#pragma unroll
                for (int mt = 0; mt < 2; mt++) {
                    mma16816(acc[mt][2 * ng],     ah[mt], th[0], th[1]);
                    mma16816(acc[mt][2 * ng],     al[mt], th[0], th[1]);
                    mma16816(acc[mt][2 * ng + 1], ah[mt], th[2], th[3]);
                    mma16816(acc[mt][2 * ng + 1], al[mt], th[2], th[3]);
                }
            }
        }
        __syncthreads();
    }

    stageB(wf3, 0, sm_sa);
    CP_COMMIT();

    // ---- epilogue 1 (registers): EPI2 then fp16 -> T ----
    {
        __half* T = reinterpret_cast<__half*>(smc + T_OFF);
#pragma unroll
        for (int nf = 0; nf < 8; nf++) {
            const int n0 = warp_n + nf * 8 + (lane & 3) * 2;
            const float sA = __ldg(&e_g[n0]) * rsqrtf(__ldg(&e_v[n0]) + EPSf);
            const float tA = __ldg(&e_b[n0]) - __ldg(&e_m[n0]) * sA;
            const float sB = __ldg(&e_g[n0 + 1]) * rsqrtf(__ldg(&e_v[n0 + 1]) + EPSf);
            const float tB = __ldg(&e_b[n0 + 1]) - __ldg(&e_m[n0 + 1]) * sB;
#pragma unroll
            for (int mt = 0; mt < 2; mt++) {
                const int m = warp_m + mt * 16 + (lane >> 2);
                int hw = pix0 + m; if (hw > HWc - 1) hw = HWc - 1;
                int h = hw / 56;
                const int rel0 = (hw - h * 56) - h + 56;
                int hw8 = pix0 + m + 8; if (hw8 > HWc - 1) hw8 = HWc - 1;
                h = hw8 / 56;
                const int rel8 = (hw8 - h * 56) - h + 56;
                const float v0 = gelu_f(acc[mt][nf][0] * sA + tA) + __ldg(&e_pos[rel0 * 128 + n0]);
                const float v1 = gelu_f(acc[mt][nf][1] * sB + tB) + __ldg(&e_pos[rel0 * 128 + n0 + 1]);
                const float v2 = gelu_f(acc[mt][nf][2] * sA + tA) + __ldg(&e_pos[rel8 * 128 + n0]);
                const float v3 = gelu_f(acc[mt][nf][3] * sB + tB) + __ldg(&e_pos[rel8 * 128 + n0 + 1]);
                T[n0 * 136 + m]            = __float2half_rn(v0);
                T[(n0 + 1) * 136 + m]      = __float2half_rn(v1);
                T[n0 * 136 + m + 8]        = __float2half_rn(v2);
                T[(n0 + 1) * 136 + m + 8]  = __float2half_rn(v3);
            }
        }
    }
    __syncthreads();

    // =================== phase 2: u1 = concat[t1, y2] @ fuse_w ===============
#pragma unroll
    for (int mt = 0; mt < 2; mt++)
#pragma unroll
        for (int nf = 0; nf < 8; nf++)
#pragma unroll
            for (int j = 0; j < 4; j++) acc[mt][nf][j] = 0.f;

    auto issue2 = [&](int kc, int buf) {
        const uint32_t base = sm_sa + buf * STG;
        if (kc >= 4) stageA(yh + 128L * HWc, yl + 128L * HWc, SF, (kc - 4) * 32, base);
        stageB(wf3, kc, base);
    };

#pragma unroll 1
    for (int kc = 0; kc < 8; kc++) {
        if (kc < 7) { issue2(kc + 1, (kc + 1) & 1); CP_COMMIT(); }
        if (kc < 7) asm volatile("cp.async.wait_group 1;" ::: "memory");
        else        asm volatile("cp.async.wait_group 0;" ::: "memory");
        __syncthreads();

        const uint32_t base = sm_sa + (kc & 1) * STG;
        if (kc < 4) {
#pragma unroll
            for (int ks = 0; ks < 2; ks++) {
                const int k0 = ks * 16;
                uint32_t ah[2][4];
#pragma unroll
                for (int half = 0; half < 2; half++) {
                    const uint32_t ea = (uint32_t)((kc * 32 + k0 + a_kr) * 136 + warp_m + half * 16 + a_mc) * 2;
                    ldsm4t(ah[half], sm_sa + T_OFF + ea);
                }
#pragma unroll
                for (int ng = 0; ng < 4; ng++) {
                    const uint32_t eb = (uint32_t)((warp_n + ng * 16 + b_nr) * 40 + k0 + b_kc) * 2;
                    uint32_t th[4];
                    ldsm4(th, base + BHB + eb);
#pragma unroll
                    for (int mt = 0; mt < 2; mt++) {
                        mma16816(acc[mt][2 * ng],     ah[mt], th[0], th[1]);
                        mma16816(acc[mt][2 * ng + 1], ah[mt], th[2], th[3]);
                    }
                }
            }
        } else {
#pragma unroll
            for (int ks = 0; ks < 2; ks++) {
                const int k0 = ks * 16;
                uint32_t ah[2][4], al[2][4];
#pragma unroll
                for (int half = 0; half < 2; half++) {
                    const uint32_t ea = (uint32_t)((k0 + a_kr) * 136 + warp_m + half * 16 + a_mc) * 2;
                    ldsm4t(ah[half], base + ea);
                    ldsm4t(al[half], base + ALB + ea);
                }
#pragma unroll
                for (int ng = 0; ng < 4; ng++) {
                    const uint32_t eb = (uint32_t)((warp_n + ng * 16 + b_nr) * 40 + k0 + b_kc) * 2;
                    uint32_t th[4];
                    ldsm4(th, base + BHB + eb);
#pragma unroll
                    for (int mt = 0; mt < 2; mt++) {
                        mma16816(acc[mt][2 * ng],     ah[mt], th[0], th[1]);
                        mma16816(acc[mt][2 * ng],     al[mt], th[0], th[1]);
                        mma16816(acc[mt][2 * ng + 1], ah[mt], th[2], th[3]);
                        mma16816(acc[mt][2 * ng + 1], al[mt], th[2], th[3]);
                    }
                }
            }
        }
        __syncthreads();
    }

    // ---- epilogue 2: u1 fp16 single via smem transpose ----
    float* O = reinterpret_cast<float*>(smc);
#pragma unroll
    for (int mt = 0; mt < 2; mt++)
#pragma unroll
        for (int nf = 0; nf < 8; nf++) {
            const int n = warp_n + nf * 8 + (lane & 3) * 2;
            const int m = warp_m + mt * 16 + (lane >> 2);
            O[n * 132 + m]           = acc[mt][nf][0];
            O[(n + 1) * 132 + m]     = acc[mt][nf][1];
            O[n * 132 + m + 8]       = acc[mt][nf][2];
            O[(n + 1) * 132 + m + 8] = acc[mt][nf][3];
        }
    __syncthreads();

    {
        const int m0 = lane * 4;
        const int hw0 = pix0 + m0;
        if (hw0 < HWc) {
#pragma unroll
            for (int r = 0; r < 16; r++) {
                const int n = wid * 16 + r;
                const float4 v = *reinterpret_cast<const float4*>(&O[n * 132 + m0]);
                const uint32_t h0 = pack_fp2(v.x, v.y);
                const uint32_t h1 = pack_fp2(v.z, v.w);
                const long eoff = (long)nimg * SH + (long)n * HWc + hw0;
                *reinterpret_cast<uint2*>(obh + eoff) = make_uint2(h0, h1);
            }
        }
    }
}

// ---------------------------------------------------------------------------
// Strip conv (unchanged).
// ---------------------------------------------------------------------------
__global__ __launch_bounds__(224)
void strip_k(const float* __restrict__ Wh, const float* __restrict__ bh,
             const float* __restrict__ Ww, const float* __restrict__ bw,
             const __half* __restrict__ yh, const __half* __restrict__ yl)
{
    __shared__ float xs[58 * 58];
    __shared__ float os[3136];
    const bool WVAR = blockIdx.x >= 64;
    const int c = blockIdx.x & 63;
    const int n = blockIdx.y;
    const int tid = threadIdx.x;
    const float* Wg = WVAR ? Ww : Wh;
    const float* bias = WVAR ? bw : bh;

    for (int i = tid; i < 58 * 58; i += 224) xs[i] = 0.f;
    __syncthreads();
    {
        const long yb = (long)n * SF + (long)((WVAR ? 64 : 0) + c) * HWc;
        for (int i = tid; i < HWc; i += 224) {
            const float v = __half2float(yh[yb + i]) + __half2float(yl[yb + i]);
            const int h = i / 56, w = i - h * 56;
            if (WVAR) xs[(1 + w) * 58 + 1 + h] = v;
            else      xs[(1 + h) * 58 + 1 + w] = v;
        }
    }
    __syncthreads();

    const int oo = tid >> 2;
    const int base0 = (tid & 3) * 14;
    const float* wrow = Wg + ((long)c * 56 + oo) * 168;

    float acc[14];
    const float bval = __ldg(&bias[c * 56 + oo]);
#pragma unroll
    for (int i = 0; i < 14; i++) acc[i] = bval;

    for (int hp = 0; hp < 56; hp++) {
        const float w0 = __ldg(&wrow[hp * 3 + 0]);
        const float w1 = __ldg(&wrow[hp * 3 + 1]);
        const float w2 = __ldg(&wrow[hp * 3 + 2]);
        const float* xr = xs + (1 + hp) * 58 + base0;
        float xv[16];
#pragma unroll
        for (int t = 0; t < 16; t++) xv[t] = xr[t];
#pragma unroll
        for (int i = 0; i < 14; i++) acc[i] += w0 * xv[i] + w1 * xv[i + 1] + w2 * xv[i + 2];
    }

    __half* cbh = (__half*)g_cbh4;
    __half* cbl = (__half*)g_cbl4;

    if (!WVAR) {
        const long dst = (long)n * SH + (long)c * HWc + oo * 56 + base0;
#pragma unroll
        for (int i = 0; i < 7; i++) {
            uint32_t hi, lo;
            split_fp2(acc[2 * i], acc[2 * i + 1], hi, lo);
            *reinterpret_cast<uint32_t*>(cbh + dst + 2 * i) = hi;
            *reinterpret_cast<uint32_t*>(cbl + dst + 2 * i) = lo;
        }
    } else {
#pragma unroll
        for (int i = 0; i < 14; i++) os[(base0 + i) * 56 + oo] = acc[i];
        __syncthreads();
        const int p0 = tid * 14;
        const long dst = (long)n * SH + (long)(64 + c) * HWc + p0;
#pragma unroll
        for (int i = 0; i < 7; i++) {
            uint32_t hi, lo;
            split_fp2(os[p0 + 2 * i], os[p0 + 2 * i + 1], hi, lo);
            *reinterpret_cast<uint32_t*>(cbh + dst + 2 * i) = hi;
            *reinterpret_cast<uint32_t*>(cbl + dst + 2 * i) = lo;
        }
    }
}

// ---------------------------------------------------------------------------
// Depthwise 3x7 + 7x3 + channel mean (unchanged).
// ---------------------------------------------------------------------------
__global__ __launch_bounds__(224)
void dw_k(const float* __restrict__ wh, const float* __restrict__ ww,
          const __half* __restrict__ yh, const __half* __restrict__ yl)
{
    __shared__ float xs[62][62];
    __shared__ float red[7];
    const int c = blockIdx.x, n = blockIdx.y;
    const int tid = threadIdx.x;

    for (int i = tid; i < 62 * 62; i += 224) ((float*)xs)[i] = 0.f;
    __syncthreads();
    const long yb = (long)n * SF + (long)(128 + c) * HWc;
    for (int i = tid; i < HWc; i += 224) {
        const int h = i / 56;
        xs[3 + h][3 + (i - h * 56)] = __half2float(yh[yb + i]) + __half2float(yl[yb + i]);
    }
    __syncthreads();

    float kh_[21], kw_[21];
#pragma unroll
    for (int i = 0; i < 21; i++) { kh_[i] = __ldg(&wh[c * 21 + i]); kw_[i] = __ldg(&ww[c * 21 + i]); }

    const int w = tid % 56;
    const int r0 = (tid / 56) * 14;

    float R[3][7], V[7][3];
#pragma unroll
    for (int a = 0; a < 3; a++)
#pragma unroll
        for (int b = 0; b < 7; b++) R[a][b] = xs[2 + r0 + a][w + b];
#pragma unroll
    for (int a = 0; a < 7; a++)
#pragma unroll
        for (int b = 0; b < 3; b++) V[a][b] = xs[r0 + a][2 + w + b];

    float lsum = 0.f;
    __half* dh = (__half*)g_x2h4 + (long)n * SH + (long)c * HWc + w;
    __half* dv = (__half*)g_x2w4 + (long)n * SH + (long)c * HWc + w;

#pragma unroll
    for (int j = 0; j < 14; j++) {
        float vh = 0.f, vw = 0.f;
#pragma unroll
        for (int a = 0; a < 3; a++)
#pragma unroll
            for (int b = 0; b < 7; b++)
                vh += kh_[a * 7 + b] * R[(j + a) % 3][b];
#pragma unroll
        for (int a = 0; a < 7; a++)
#pragma unroll
            for (int b = 0; b < 3; b++)
                vw += kw_[a * 3 + b] * V[(j + a) % 7][b];
        const float cen = R[(j + 1) % 3][3];
        dh[(r0 + j) * 56] = __float2half_rn(vh);
        dv[(r0 + j) * 56] = __float2half_rn(vw);
        lsum += vh + vw + cen;
        if (j < 13) {
#pragma unroll
            for (int b = 0; b < 7; b++) R[j % 3][b] = xs[2 + r0 + j + 3][w + b];
#pragma unroll
            for (int b = 0; b < 3; b++) V[j % 7][b] = xs[r0 + j + 7][2 + w + b];
        }
    }

#pragma unroll
    for (int off = 16; off; off >>= 1) lsum += __shfl_down_sync(0xffffffffu, lsum, off);
    if ((tid & 31) == 0) red[tid >> 5] = lsum;
    __syncthreads();
    if (tid == 0) {
        float s = 0.f;
#pragma unroll
        for (int i = 0; i < 7; i++) s += red[i];
        g_att[n * 128 + c] = s * (1.0f / HWc);
    }
}

// ---------------------------------------------------------------------------
// Tiny attention MLP (unchanged).
// ---------------------------------------------------------------------------
__global__ __launch_bounds__(128)
void att_k(const float* __restrict__ w1, const float* __restrict__ b1,
           const float* __restrict__ w2, const float* __restrict__ b2)
{
    __shared__ float satt[128];
    __shared__ float shid[64];
    const int n = blockIdx.x, tid = threadIdx.x;
    satt[tid] = g_att[n * 128 + tid];
    __syncthreads();
    if (tid < 64) {
        float acc = b1[tid];
        for (int c = 0; c < 128; c++) acc += satt[c] * w1[tid * 128 + c];
        shid[tid] = gelu_f(acc);
    }
    __syncthreads();
    float v[3];
#pragma unroll
    for (int k = 0; k < 3; k++) {
        float acc = b2[tid * 3 + k];
        for (int h = 0; h < 64; h++) acc += shid[h] * w2[(tid * 3 + k) * 64 + h];
        v[k] = acc;
    }
    const float m = fmaxf(v[0], fmaxf(v[1], v[2]));
    const float e0 = expf(v[0] - m), e1 = expf(v[1] - m), e2 = expf(v[2] - m);
    const float s = e0 + e1 + e2;
    g_a[n * 384 + tid * 3 + 0] = e0 / s;
    g_a[n * 384 + tid * 3 + 1] = e1 / s;
    g_a[n * 384 + tid * 3 + 2] = e2 / s;
}

// ---------------------------------------------------------------------------
extern "C" void kernel_launch(void* const* d_in, const int* in_sizes, int n_in,
                              void* d_out, int out_size)
{
    const float* x      = (const float*)d_in[0];
    const float* mlp_w  = (const float*)d_in[1];
    const float* mlp_b  = (const float*)d_in[2];
    const float* bn1_g  = (const float*)d_in[3];
    const float* bn1_b  = (const float*)d_in[4];
    const float* bn1_m  = (const float*)d_in[5];
    const float* bn1_v  = (const float*)d_in[6];
    const float* pos_h  = (const float*)d_in[7];
    const float* pos_w  = (const float*)d_in[8];
    const float* pjh_w  = (const float*)d_in[9];
    const float* pjh_b  = (const float*)d_in[10];
    const float* pjw_w  = (const float*)d_in[11];
    const float* pjw_b  = (const float*)d_in[12];
    const float* fuse_h = (const float*)d_in[13];
    const float* bn2_g  = (const float*)d_in[14];
    const float* bn2_b  = (const float*)d_in[15];
    const float* bn2_m  = (const float*)d_in[16];
    const float* bn2_v  = (const float*)d_in[17];
    const float* fuse_w = (const float*)d_in[18];
    const float* fch_w  = (const float*)d_in[19];
    const float* fcw_w  = (const float*)d_in[20];
    const float* rw_w1  = (const float*)d_in[21];
    const float* rw_b1  = (const float*)d_in[22];
    const float* rw_w2  = (const float*)d_in[23];
    const float* rw_b2  = (const float*)d_in[24];
    const float* fout_w = (const float*)d_in[25];

    float *ap;
    void *ybh, *ybl, *cbh, *cbl, *u1h, *x2hp, *x2wp, *wfp;
    cudaGetSymbolAddress((void**)&ap, g_a);
    cudaGetSymbolAddress(&ybh, g_ybh4);
    cudaGetSymbolAddress(&ybl, g_ybl4);
    cudaGetSymbolAddress(&cbh, g_cbh4);
    cudaGetSymbolAddress(&cbl, g_cbl4);
    cudaGetSymbolAddress(&u1h, g_u1h4);
    cudaGetSymbolAddress(&x2hp, g_x2h4);
    cudaGetSymbolAddress(&x2wp, g_x2w4);
    cudaGetSymbolAddress(&wfp, g_wf4);

    const __half* WF = (const __half*)wfp;

    cudaFuncSetAttribute(tc_gemm<1,1,2>, cudaFuncAttributeMaxDynamicSharedMemorySize, SMEM_GEMM);
    cudaFuncSetAttribute(tc_gemm<2,0,0>, cudaFuncAttributeMaxDynamicSharedMemorySize, SMEM_GEMM);
    cudaFuncSetAttribute(tc_g23, cudaFuncAttributeMaxDynamicSharedMemorySize, SMEM_G23);

    wprep_k<<<dim3(6, 8), 256>>>(mlp_w, fuse_h, fuse_w, fout_w);

    // GEMM1: y = gelu(bn(x@mlp_w + b)), ch<128 += pos_h ; fp16 hi/lo out
    tc_gemm<1,1,2><<<dim3(2, NPB), 256, SMEM_GEMM>>>(
        WF, nullptr, 0, nullptr, nullptr, 0,
        x, SF, nullptr, 0,
        (__half*)ybh, (__half*)ybl, SF,
        mlp_b, bn1_g, bn1_b, bn1_m, bn1_v, pos_h, nullptr, nullptr, nullptr);

    strip_k<<<dim3(128, 16), 224>>>(pjh_w, pjh_b, pjw_w, pjw_b,
        (const __half*)ybh, (const __half*)ybl);
    dw_k<<<dim3(128, 16), 224>>>(fch_w, fcw_w,
        (const __half*)ybh, (const __half*)ybl);
    att_k<<<16, 128>>>(rw_w1, rw_b1, rw_w2, rw_b2);

    // Fused GEMM2+3 -> u1 (fp16 single)
    tc_g23<<<dim3(1, NPB), 256, SMEM_G23>>>(
        WF + 2L * 40960, WF + 3L * 40960,
        (const __half*)cbh, (const __half*)cbl,
        (const __half*)ybh, (const __half*)ybl,
        (__half*)u1h,
        bn2_g, bn2_b, bn2_m, bn2_v, pos_w);

    // GEMM4 (1-term A): out = concat[u1, a0*x2h + a1*x2w + a2*y2]@fuse_out
    tc_gemm<2,0,0><<<dim3(2, NPB), 256, SMEM_GEMM>>>(
        WF + 4L * 40960,
        (const __half*)u1h, SH,
        (const __half*)ybh + 128L * HWc, (const __half*)ybl + 128L * HWc, SF,
        nullptr, 0, (float*)d_out, SF,
        nullptr, nullptr, 0,
        nullptr, nullptr, nullptr, nullptr, nullptr, nullptr,
        (const __half*)x2hp, (const __half*)x2wp, ap);
}

// round 14
// speedup vs baseline: 1.0681x; 1.0681x over previous
#include <cuda_runtime.h>
#include <cuda_fp16.h>
#include <math.h>
#include <stdint.h>

#define Nn   16
#define Cc   256
#define C1c  128
#define HWc  3136
#define EPSf 1e-5f
#define PBI  25
#define NPB  (Nn*PBI)
#define SF   (Cc*HWc)
#define SH   (C1c*HWc)

// ---------------- scratch (device globals; no allocations) ----------------
__device__ float g_att[Nn*C1c];
__device__ float g_a  [Nn*C1c*3];

__device__ uint4 g_ybh4[(Nn*Cc *HWc + 256) / 8];
__device__ uint4 g_ybl4[(Nn*Cc *HWc + 256) / 8];
__device__ uint4 g_cbh4[(Nn*C1c*HWc + 256) / 8];
__device__ uint4 g_cbl4[(Nn*C1c*HWc + 256) / 8];
__device__ uint4 g_u1h4[(Nn*C1c*HWc + 256) / 8];
__device__ uint4 g_u1l4[(Nn*C1c*HWc + 256) / 8];
__device__ uint4 g_x2h4[(Nn*C1c*HWc + 256) / 8];
__device__ uint4 g_x2w4[(Nn*C1c*HWc + 256) / 8];
// prepped weights (fp16): 6 slots x 8 chunks x [128 n][40 halves]
__device__ uint4 g_wf4[6 * 40960 / 8];

__device__ __forceinline__ float gelu_f(float x) {
    return 0.5f * x * (1.0f + erff(x * 0.7071067811865476f));
}
__device__ __forceinline__ uint32_t smem_to_u32(const void* p) {
    uint32_t a;
    asm("{ .reg .u64 t; cvta.to.shared.u64 t, %1; cvt.u32.u64 %0, t; }" : "=r"(a) : "l"(p));
    return a;
}
__device__ __forceinline__ void split_fp2(float x0, float x1, uint32_t& hi, uint32_t& lo) {
    const __half h0 = __float2half_rn(x0);
    const __half h1 = __float2half_rn(x1);
    const __half l0 = __float2half_rn(x0 - __half2float(h0));
    const __half l1 = __float2half_rn(x1 - __half2float(h1));
    hi = (uint32_t)__half_as_ushort(h0) | ((uint32_t)__half_as_ushort(h1) << 16);
    lo = (uint32_t)__half_as_ushort(l0) | ((uint32_t)__half_as_ushort(l1) << 16);
}
__device__ __forceinline__ uint32_t pack_fp2(float x0, float x1) {
    const __half h0 = __float2half_rn(x0);
    const __half h1 = __float2half_rn(x1);
    return (uint32_t)__half_as_ushort(h0) | ((uint32_t)__half_as_ushort(h1) << 16);
}
__device__ __forceinline__ void ldsm4(uint32_t (&r)[4], uint32_t addr) {
    asm volatile("ldmatrix.sync.aligned.m8n8.x4.shared.b16 {%0,%1,%2,%3}, [%4];"
        : "=r"(r[0]), "=r"(r[1]), "=r"(r[2]), "=r"(r[3]) : "r"(addr));
}
__device__ __forceinline__ void ldsm4t(uint32_t (&r)[4], uint32_t addr) {
    asm volatile("ldmatrix.sync.aligned.m8n8.x4.trans.shared.b16 {%0,%1,%2,%3}, [%4];"
        : "=r"(r[0]), "=r"(r[1]), "=r"(r[2]), "=r"(r[3]) : "r"(addr));
}
__device__ __forceinline__ void mma16816(float (&c)[4], const uint32_t (&a)[4], uint32_t b0, uint32_t b1) {
    asm volatile("mma.sync.aligned.m16n8k16.row.col.f32.f16.f16.f32 "
        "{%0,%1,%2,%3}, {%4,%5,%6,%7}, {%8,%9}, {%0,%1,%2,%3};"
        : "+f"(c[0]), "+f"(c[1]), "+f"(c[2]), "+f"(c[3])
        : "r"(a[0]), "r"(a[1]), "r"(a[2]), "r"(a[3]), "r"(b0), "r"(b1));
}
#define CP16(dst, src) asm volatile("cp.async.cg.shared.global [%0], [%1], 16;" :: "r"(dst), "l"(src))
#define CP_COMMIT()    asm volatile("cp.async.commit_group;" ::: "memory")

// ---------------------------------------------------------------------------
// Weight prep (unchanged).
// ---------------------------------------------------------------------------
__global__ __launch_bounds__(256)
void wprep_k(const float* __restrict__ mlp_w, const float* __restrict__ fuse_h,
             const float* __restrict__ fuse_w, const float* __restrict__ fout_w)
{
    const int slot = blockIdx.x, kc = blockIdx.y, tid = threadIdx.x;
    const float* W; int o0;
    switch (slot) {
        case 0: W = mlp_w;  o0 = 0;   break;
        case 1: W = mlp_w;  o0 = 128; break;
        case 2: W = fuse_h; o0 = 0;   break;
        case 3: W = fuse_w; o0 = 0;   break;
        case 4: W = fout_w; o0 = 0;   break;
        default:W = fout_w; o0 = 128; break;
    }
    const int n = tid >> 1;
    const int kh = (tid & 1) * 16;
    const float* src = W + (long)(o0 + n) * 256 + kc * 32 + kh;
    uint32_t hp[8];
#pragma unroll
    for (int j = 0; j < 8; j++) {
        const float2 v = *reinterpret_cast<const float2*>(src + 2 * j);
        hp[j] = pack_fp2(v.x, v.y);
    }
    __half* dh = (__half*)g_wf4 + (long)slot * 40960 + kc * 5120 + n * 40 + kh;
    *reinterpret_cast<uint4*>(dh)     = *reinterpret_cast<uint4*>(&hp[0]);
    *reinterpret_cast<uint4*>(dh + 8) = *reinterpret_cast<uint4*>(&hp[4]);
    if (tid < 128) {
        const uint4 z = {0, 0, 0, 0};
        *reinterpret_cast<uint4*>((__half*)g_wf4 + (long)slot * 40960 + kc * 5120 + tid * 40 + 32) = z;
    }
}

// ---------------------------------------------------------------------------
// Generic GEMM (exact R12 geometry: 2-term everywhere).
// APATH: 1 fp32 convert (GEMM1); 2 GEMM4 (u1 hi/lo chunks 0-3, comb chunks 4-7)
// EPI: 0 none; 1 +bias,BN,gelu,+pos(o<128). OUT: 0 fp32; 2 fp16 hi/lo.
// ---------------------------------------------------------------------------
#define STG 27648
#define ALB 8704
#define BHB 17408
#define SMEM_GEMM 67584

template<int APATH, int EPI, int OUT>
__global__ __launch_bounds__(256, 2)
void tc_gemm(const __half* __restrict__ wf,
             const __half* __restrict__ s1h, const __half* __restrict__ s1l, int str1,
             const __half* __restrict__ s2h, const __half* __restrict__ s2l, int str2,
             const float* __restrict__ xin, int strX,
             float* __restrict__ out, int strO,
             __half* __restrict__ obh, __half* __restrict__ obl, int strOB,
             const float* __restrict__ e_bias,
             const float* __restrict__ e_g, const float* __restrict__ e_b,
             const float* __restrict__ e_m, const float* __restrict__ e_v,
             const float* __restrict__ e_pos,
             const __half* __restrict__ cH, const __half* __restrict__ cW,
             const float* __restrict__ cA)
{
    extern __shared__ __align__(16) char smc[];
    const uint32_t sm_sa = smem_to_u32(smc);

    const int tid = threadIdx.x;
    const int wid = tid >> 5;
    const int lane = tid & 31;
    const int o0 = blockIdx.x * 128;
    const int nimg = blockIdx.y / PBI;
    const int pix0 = (blockIdx.y % PBI) * 128;
    const int warp_m = (wid & 3) * 32;
    const int warp_n = (wid >> 2) * 64;

    const __half* wfB = wf + (long)blockIdx.x * 40960;

    const int pix2 = tid & 63;
    const int rgrp = tid >> 6;
    int p0 = pix0 + 2 * pix2;
    if (p0 > HWc - 2) p0 = HWc - 2;

    auto issue = [&](int kc, int buf) {
        const uint32_t base = sm_sa + buf * STG;
        char* bp = smc + buf * STG;
        if (APATH == 1) {
            const float* src = xin + (long)nimg * strX + p0;
#pragma unroll
            for (int j = 0; j < 8; j++) {
                const int r = rgrp + 4 * j;
                const float2 v = *reinterpret_cast<const float2*>(src + (long)(kc * 32 + r) * HWc);
                uint32_t hi, lo;
                split_fp2(v.x, v.y, hi, lo);
                *reinterpret_cast<uint32_t*>(bp + r * 272 + pix2 * 4) = hi;
                *reinterpret_cast<uint32_t*>(bp + ALB + r * 272 + pix2 * 4) = lo;
            }
        } else if (kc < 4) {
            const long chb = (long)nimg * str1 + (long)(kc * 32) * HWc + pix0;
#pragma unroll
            for (int it = 0; it < 2; it++) {
                const int idx = tid + it * 256;
                const int row = idx >> 4, seg = idx & 15;
                const char* gh = (const char*)(s1h + chb + (long)row * HWc) + seg * 16;
                const char* gl = (const char*)(s1l + chb + (long)row * HWc) + seg * 16;
                CP16(base + row * 272 + seg * 16, gh);
                CP16(base + ALB + row * 272 + seg * 16, gl);
            }
        } else {
            const long ib = (long)nimg * SH + p0;
            const __half* pH = cH + ib;
            const __half* pW = cW + ib;
            const __half* pXh = s2h + (long)nimg * str2 + p0;
            const __half* pXl = s2l + (long)nimg * str2 + p0;
            const float* aB = cA + nimg * 384;
#pragma unroll
            for (int j = 0; j < 8; j++) {
                const int r = rgrp + 4 * j;
                const int cc = (kc - 4) * 32 + r;
                const float a0 = aB[cc * 3], a1 = aB[cc * 3 + 1], a2 = aB[cc * 3 + 2];
                const __half2 vh2 = *reinterpret_cast<const __half2*>(pH + (long)cc * HWc);
                const __half2 vw2 = *reinterpret_cast<const __half2*>(pW + (long)cc * HWc);
                const __half2 xh2 = *reinterpret_cast<const __half2*>(pXh + (long)cc * HWc);
                const __half2 xl2 = *reinterpret_cast<const __half2*>(pXl + (long)cc * HWc);
                float2 v;
                v.x = a0 * __half2float(vh2.x) + a1 * __half2float(vw2.x)
                    + a2 * (__half2float(xh2.x) + __half2float(xl2.x));
                v.y = a0 * __half2float(vh2.y) + a1 * __half2float(vw2.y)
                    + a2 * (__half2float(xh2.y) + __half2float(xl2.y));
                uint32_t hi, lo;
                split_fp2(v.x, v.y, hi, lo);
                *reinterpret_cast<uint32_t*>(bp + r * 272 + pix2 * 4) = hi;
                *reinterpret_cast<uint32_t*>(bp + ALB + r * 272 + pix2 * 4) = lo;
            }
        }
        const char* wsrc = (const char*)(wfB + kc * 5120);
#pragma unroll
        for (int it = 0; it < 3; it++) {
            const int i = tid + it * 256;
            if (i < 640) CP16(base + BHB + i * 16, wsrc + i * 16);
        }
    };

    const int a_kr = (lane & 7) + ((lane & 16) >> 1);
    const int a_mc = (lane & 8);
    const int b_nr = (lane & 7) + ((lane & 16) >> 1);
    const int b_kc = (lane & 8);

    float acc[2][8][4];
#pragma unroll
    for (int mt = 0; mt < 2; mt++)
#pragma unroll
        for (int nf = 0; nf < 8; nf++)
#pragma unroll
            for (int j = 0; j < 4; j++) acc[mt][nf][j] = 0.f;

    issue(0, 0);
    CP_COMMIT();

#pragma unroll 1
    for (int kc = 0; kc < 8; kc++) {
        if (kc < 7) { issue(kc + 1, (kc + 1) & 1); CP_COMMIT(); }
        if (kc < 7) asm volatile("cp.async.wait_group 1;" ::: "memory");
        else        asm volatile("cp.async.wait_group 0;" ::: "memory");
        __syncthreads();

        const uint32_t base = sm_sa + (kc & 1) * STG;
#pragma unroll
        for (int ks = 0; ks < 2; ks++) {
            const int k0 = ks * 16;
            uint32_t ah[2][4], al[2][4];
#pragma unroll
            for (int half = 0; half < 2; half++) {
                const uint32_t ea = (uint32_t)((k0 + a_kr) * 136 + warp_m + half * 16 + a_mc) * 2;
                ldsm4t(ah[half], base + ea);
                ldsm4t(al[half], base + ALB + ea);
            }
#pragma unroll
            for (int ng = 0; ng < 4; ng++) {
                const uint32_t eb = (uint32_t)((warp_n + ng * 16 + b_nr) * 40 + k0 + b_kc) * 2;
                uint32_t th[4];
                ldsm4(th, base + BHB + eb);
#pragma unroll
                for (int mt = 0; mt < 2; mt++) {
                    mma16816(acc[mt][2 * ng],     ah[mt], th[0], th[1]);
                    mma16816(acc[mt][2 * ng],     al[mt], th[0], th[1]);
                    mma16816(acc[mt][2 * ng + 1], ah[mt], th[2], th[3]);
                    mma16816(acc[mt][2 * ng + 1], al[mt], th[2], th[3]);
                }
            }
        }
        __syncthreads();
    }

    // ---- epilogue ----
    float* O = reinterpret_cast<float*>(smc);
#pragma unroll
    for (int mt = 0; mt < 2; mt++)
#pragma unroll
        for (int nf = 0; nf < 8; nf++) {
            const int n = warp_n + nf * 8 + (lane & 3) * 2;
            const int m = warp_m + mt * 16 + (lane >> 2);
            O[n * 132 + m]           = acc[mt][nf][0];
            O[(n + 1) * 132 + m]     = acc[mt][nf][1];
            O[n * 132 + m + 8]       = acc[mt][nf][2];
            O[(n + 1) * 132 + m + 8] = acc[mt][nf][3];
        }
    __syncthreads();

    {
        const int m0 = lane * 4;
        const int hw0 = pix0 + m0;
        const bool pvalid = (hw0 < HWc);
        int rel[4] = {0, 0, 0, 0};
        if (pvalid && EPI != 0) {
#pragma unroll
            for (int j = 0; j < 4; j++) {
                const int hwj = hw0 + j;
                const int h = hwj / 56;
                rel[j] = (hwj - h * 56) - h + 56;
            }
        }
        if (pvalid) {
#pragma unroll
            for (int r = 0; r < 16; r++) {
                const int n = wid * 16 + r;
                const int o = o0 + n;
                const float4 v = *reinterpret_cast<const float4*>(&O[n * 132 + m0]);
                float vv[4] = {v.x, v.y, v.z, v.w};
                if (EPI == 1) {
                    const float s = __ldg(&e_g[o]) * rsqrtf(__ldg(&e_v[o]) + EPSf);
                    const float t = __ldg(&e_b[o]) - __ldg(&e_m[o]) * s;
                    const float bb = __ldg(&e_bias[o]);
#pragma unroll
                    for (int j = 0; j < 4; j++) {
                        float u = gelu_f((vv[j] + bb) * s + t);
                        if (o < 128) u += __ldg(&e_pos[rel[j] * 128 + o]);
                        vv[j] = u;
                    }
                }
                if (OUT != 2) {
                    float4 ov;
                    ov.x = vv[0]; ov.y = vv[1]; ov.z = vv[2]; ov.w = vv[3];
                    *reinterpret_cast<float4*>(&out[(long)nimg * strO + (long)o * HWc + hw0]) = ov;
                }
                if (OUT != 0) {
                    uint32_t h0, l0, h1, l1;
                    split_fp2(vv[0], vv[1], h0, l0);
                    split_fp2(vv[2], vv[3], h1, l1);
                    const long eoff = (long)nimg * strOB + (long)o * HWc + hw0;
                    *reinterpret_cast<uint2*>(obh + eoff) = make_uint2(h0, h1);
                    *reinterpret_cast<uint2*>(obl + eoff) = make_uint2(l0, l1);
                }
            }
        }
    }
}

// ---------------------------------------------------------------------------
// Fused GEMM2+GEMM3 (exact R12 version: u1 out fp16 hi/lo).
// ---------------------------------------------------------------------------
#define T_OFF 55296
#define SMEM_G23 90112

__global__ __launch_bounds__(256, 2)
void tc_g23(const __half* __restrict__ wf2, const __half* __restrict__ wf3,
            const __half* __restrict__ s1h, const __half* __restrict__ s1l,
            const __half* __restrict__ yh, const __half* __restrict__ yl,
            __half* __restrict__ obh, __half* __restrict__ obl,
            const float* __restrict__ e_g, const float* __restrict__ e_b,
            const float* __restrict__ e_m, const float* __restrict__ e_v,
            const float* __restrict__ e_pos)
{
    extern __shared__ __align__(16) char smc[];
    const uint32_t sm_sa = smem_to_u32(smc);

    const int tid = threadIdx.x;
    const int wid = tid >> 5;
    const int lane = tid & 31;
    const int nimg = blockIdx.y / PBI;
    const int pix0 = (blockIdx.y % PBI) * 128;
    const int warp_m = (wid & 3) * 32;
    const int warp_n = (wid >> 2) * 64;

    const int a_kr = (lane & 7) + ((lane & 16) >> 1);
    const int a_mc = (lane & 8);
    const int b_nr = (lane & 7) + ((lane & 16) >> 1);
    const int b_kc = (lane & 8);

    auto stageA = [&](const __half* sh, const __half* sl, int str, int c0, uint32_t base) {
        const long chb = (long)nimg * str + (long)c0 * HWc + pix0;
#pragma unroll
        for (int it = 0; it < 2; it++) {
            const int idx = tid + it * 256;
            const int row = idx >> 4, seg = idx & 15;
            const char* gh = (const char*)(sh + chb + (long)row * HWc) + seg * 16;
            const char* gl = (const char*)(sl + chb + (long)row * HWc) + seg * 16;
            CP16(base + row * 272 + seg * 16, gh);
            CP16(base + ALB + row * 272 + seg * 16, gl);
        }
    };
    auto stageB = [&](const __half* wf, int kc, uint32_t base) {
        const char* wsrc = (const char*)(wf + kc * 5120);
#pragma unroll
        for (int it = 0; it < 3; it++) {
            const int i = tid + it * 256;
            if (i < 640) CP16(base + BHB + i * 16, wsrc + i * 16);
        }
    };

    float acc[2][8][4];
#pragma unroll
    for (int mt = 0; mt < 2; mt++)
#pragma unroll
        for (int nf = 0; nf < 8; nf++)
#pragma unroll
            for (int j = 0; j < 4; j++) acc[mt][nf][j] = 0.f;

    auto issue1 = [&](int kc, int buf) {
        const uint32_t base = sm_sa + buf * STG;
        if (kc < 4) stageA(s1h, s1l, SH, kc * 32, base);
        else        stageA(yh,  yl,  SF, (kc - 4) * 32, base);
        stageB(wf2, kc, base);
    };

    issue1(0, 0);
    CP_COMMIT();

#pragma unroll 1
    for (int kc = 0; kc < 8; kc++) {
        if (kc < 7) { issue1(kc + 1, (kc + 1) & 1); CP_COMMIT(); }
        if (kc < 7) asm volatile("cp.async.wait_group 1;" ::: "memory");
        else        asm volatile("cp.async.wait_group 0;" ::: "memory");
        __syncthreads();

        const uint32_t base = sm_sa + (kc & 1) * STG;
#pragma unroll
        for (int ks = 0; ks < 2; ks++) {
            const int k0 = ks * 16;
            uint32_t ah[2][4], al[2][4];
#pragma unroll
            for (int half = 0; half < 2; half++) {
                const uint32_t ea = (uint32_t)((k0 + a_kr) * 136 + warp_m + half * 16 + a_mc) * 2;
                ldsm4t(ah[half], base + ea);
                ldsm4t(al[half], base + ALB + ea);
            }
#pragma unroll
            for (int ng = 0; ng < 4; ng++) {
                const uint32_t eb = (uint32_t)((warp_n + ng * 16 + b_nr) * 40 + k0 + b_kc) * 2;
                uint32_t th[4];
                ldsm4(th, base + BHB + eb);
#pragma unroll
                for (int mt = 0; mt < 2; mt++) {
                    mma16816(acc[mt][2 * ng],     ah[mt], th[0], th[1]);
                    mma16816(acc[mt][2 * ng],     al[mt], th[0], th[1]);
                    mma16816(acc[mt][2 * ng + 1], ah[mt], th[2], th[3]);
                    mma16816(acc[mt][2 * ng + 1], al[mt], th[2], th[3]);
                }
            }
        }
        __syncthreads();
    }

    stageB(wf3, 0, sm_sa);
    CP_COMMIT();

    {
        __half* T = reinterpret_cast<__half*>(smc + T_OFF);
#pragma unroll
        for (int nf = 0; nf < 8; nf++) {
            const int n0 = warp_n + nf * 8 + (lane & 3) * 2;
            const float sA = __ldg(&e_g[n0]) * rsqrtf(__ldg(&e_v[n0]) + EPSf);
            const float tA = __ldg(&e_b[n0]) - __ldg(&e_m[n0]) * sA;
            const float sB = __ldg(&e_g[n0 + 1]) * rsqrtf(__ldg(&e_v[n0 + 1]) + EPSf);
            const float tB = __ldg(&e_b[n0 + 1]) - __ldg(&e_m[n0 + 1]) * sB;
#pragma unroll
            for (int mt = 0; mt < 2; mt++) {
                const int m = warp_m + mt * 16 + (lane >> 2);
                int hw = pix0 + m; if (hw > HWc - 1) hw = HWc - 1;
                int h = hw / 56;
                const int rel0 = (hw - h * 56) - h + 56;
                int hw8 = pix0 + m + 8; if (hw8 > HWc - 1) hw8 = HWc - 1;
                h = hw8 / 56;
                const int rel8 = (hw8 - h * 56) - h + 56;
                const float v0 = gelu_f(acc[mt][nf][0] * sA + tA) + __ldg(&e_pos[rel0 * 128 + n0]);
                const float v1 = gelu_f(acc[mt][nf][1] * sB + tB) + __ldg(&e_pos[rel0 * 128 + n0 + 1]);
                const float v2 = gelu_f(acc[mt][nf][2] * sA + tA) + __ldg(&e_pos[rel8 * 128 + n0]);
                const float v3 = gelu_f(acc[mt][nf][3] * sB + tB) + __ldg(&e_pos[rel8 * 128 + n0 + 1]);
                T[n0 * 136 + m]            = __float2half_rn(v0);
                T[(n0 + 1) * 136 + m]      = __float2half_rn(v1);
                T[n0 * 136 + m + 8]        = __float2half_rn(v2);
                T[(n0 + 1) * 136 + m + 8]  = __float2half_rn(v3);
            }
        }
    }
    __syncthreads();

#pragma unroll
    for (int mt = 0; mt < 2; mt++)
#pragma unroll
        for (int nf = 0; nf < 8; nf++)
#pragma unroll
            for (int j = 0; j < 4; j++) acc[mt][nf][j] = 0.f;

    auto issue2 = [&](int kc, int buf) {
        const uint32_t base = sm_sa + buf * STG;
        if (kc >= 4) stageA(yh + 128L * HWc, yl + 128L * HWc, SF, (kc - 4) * 32, base);
        stageB(wf3, kc, base);
    };

#pragma unroll 1
    for (int kc = 0; kc < 8; kc++) {
        if (kc < 7) { issue2(kc + 1, (kc + 1) & 1); CP_COMMIT(); }
        if (kc < 7) asm volatile("cp.async.wait_group 1;" ::: "memory");
        else        asm volatile("cp.async.wait_group 0;" ::: "memory");
        __syncthreads();

        const uint32_t base = sm_sa + (kc & 1) * STG;
        if (kc < 4) {
#pragma unroll
            for (int ks = 0; ks < 2; ks++) {
                const int k0 = ks * 16;
                uint32_t ah[2][4];
#pragma unroll
                for (int half = 0; half < 2; half++) {
                    const uint32_t ea = (uint32_t)((kc * 32 + k0 + a_kr) * 136 + warp_m + half * 16 + a_mc) * 2;
                    ldsm4t(ah[half], sm_sa + T_OFF + ea);
                }
#pragma unroll
                for (int ng = 0; ng < 4; ng++) {
                    const uint32_t eb = (uint32_t)((warp_n + ng * 16 + b_nr) * 40 + k0 + b_kc) * 2;
                    uint32_t th[4];
                    ldsm4(th, base + BHB + eb);
#pragma unroll
                    for (int mt = 0; mt < 2; mt++) {
                        mma16816(acc[mt][2 * ng],     ah[mt], th[0], th[1]);
                        mma16816(acc[mt][2 * ng + 1], ah[mt], th[2], th[3]);
                    }
                }
            }
        } else {
#pragma unroll
            for (int ks = 0; ks < 2; ks++) {
                const int k0 = ks * 16;
                uint32_t ah[2][4], al[2][4];
#pragma unroll
                for (int half = 0; half < 2; half++) {
                    const uint32_t ea = (uint32_t)((k0 + a_kr) * 136 + warp_m + half * 16 + a_mc) * 2;
                    ldsm4t(ah[half], base + ea);
                    ldsm4t(al[half], base + ALB + ea);
                }
#pragma unroll
                for (int ng = 0; ng < 4; ng++) {
                    const uint32_t eb = (uint32_t)((warp_n + ng * 16 + b_nr) * 40 + k0 + b_kc) * 2;
                    uint32_t th[4];
                    ldsm4(th, base + BHB + eb);
#pragma unroll
                    for (int mt = 0; mt < 2; mt++) {
                        mma16816(acc[mt][2 * ng],     ah[mt], th[0], th[1]);
                        mma16816(acc[mt][2 * ng],     al[mt], th[0], th[1]);
                        mma16816(acc[mt][2 * ng + 1], ah[mt], th[2], th[3]);
                        mma16816(acc[mt][2 * ng + 1], al[mt], th[2], th[3]);
                    }
                }
            }
        }
        __syncthreads();
    }

    float* O = reinterpret_cast<float*>(smc);
#pragma unroll
    for (int mt = 0; mt < 2; mt++)
#pragma unroll
        for (int nf = 0; nf < 8; nf++) {
            const int n = warp_n + nf * 8 + (lane & 3) * 2;
            const int m = warp_m + mt * 16 + (lane >> 2);
            O[n * 132 + m]           = acc[mt][nf][0];
            O[(n + 1) * 132 + m]     = acc[mt][nf][1];
            O[n * 132 + m + 8]       = acc[mt][nf][2];
            O[(n + 1) * 132 + m + 8] = acc[mt][nf][3];
        }
    __syncthreads();

    {
        const int m0 = lane * 4;
        const int hw0 = pix0 + m0;
        if (hw0 < HWc) {
#pragma unroll
            for (int r = 0; r < 16; r++) {
                const int n = wid * 16 + r;
                const float4 v = *reinterpret_cast<const float4*>(&O[n * 132 + m0]);
                uint32_t h0, l0, h1, l1;
                split_fp2(v.x, v.y, h0, l0);
                split_fp2(v.z, v.w, h1, l1);
                const long eoff = (long)nimg * SH + (long)n * HWc + hw0;
                *reinterpret_cast<uint2*>(obh + eoff) = make_uint2(h0, h1);
                *reinterpret_cast<uint2*>(obl + eoff) = make_uint2(l0, l1);
            }
        }
    }
}

// ---------------------------------------------------------------------------
// Merged strip + depthwise kernel. blockIdx.x: 0-63 strip-H, 64-127 strip-W,
// 128-255 depthwise. 224 threads, <=26KB smem union -> 8 CTAs/SM.
// ---------------------------------------------------------------------------
__global__ __launch_bounds__(224)
void sd_k(const float* __restrict__ Wh, const float* __restrict__ bh,
          const float* __restrict__ Ww, const float* __restrict__ bw,
          const float* __restrict__ dwh, const float* __restrict__ dww,
          const __half* __restrict__ yh, const __half* __restrict__ yl)
{
    __shared__ float sm[6500];   // strip: xs[3364]+os[3136]; dw: xs[3844]+red[7]
    const int n = blockIdx.y;
    const int tid = threadIdx.x;

    if (blockIdx.x < 128) {
        // ======================= strip conv =======================
        float* xs = sm;
        float* os = sm + 3364;
        const bool WVAR = blockIdx.x >= 64;
        const int c = blockIdx.x & 63;
        const float* Wg = WVAR ? Ww : Wh;
        const float* bias = WVAR ? bw : bh;

        for (int i = tid; i < 3364; i += 224) xs[i] = 0.f;
        __syncthreads();
        {
            const long yb = (long)n * SF + (long)((WVAR ? 64 : 0) + c) * HWc;
            for (int i = tid; i < HWc; i += 224) {
                const float v = __half2float(yh[yb + i]) + __half2float(yl[yb + i]);
                const int h = i / 56, w = i - h * 56;
                if (WVAR) xs[(1 + w) * 58 + 1 + h] = v;
                else      xs[(1 + h) * 58 + 1 + w] = v;
            }
        }
        __syncthreads();

        const int oo = tid >> 2;
        const int base0 = (tid & 3) * 14;
        const float* wrow = Wg + ((long)c * 56 + oo) * 168;

        float acc[14];
        const float bval = __ldg(&bias[c * 56 + oo]);
#pragma unroll
        for (int i = 0; i < 14; i++) acc[i] = bval;

        for (int hp = 0; hp < 56; hp++) {
            const float w0 = __ldg(&wrow[hp * 3 + 0]);
            const float w1 = __ldg(&wrow[hp * 3 + 1]);
            const float w2 = __ldg(&wrow[hp * 3 + 2]);
            const float* xr = xs + (1 + hp) * 58 + base0;
            float xv[16];
#pragma unroll
            for (int t = 0; t < 16; t++) xv[t] = xr[t];
#pragma unroll
            for (int i = 0; i < 14; i++) acc[i] += w0 * xv[i] + w1 * xv[i + 1] + w2 * xv[i + 2];
        }

        __half* cbh = (__half*)g_cbh4;
        __half* cbl = (__half*)g_cbl4;

        if (!WVAR) {
            const long dst = (long)n * SH + (long)c * HWc + oo * 56 + base0;
#pragma unroll
            for (int i = 0; i < 7; i++) {
                uint32_t hi, lo;
                split_fp2(acc[2 * i], acc[2 * i + 1], hi, lo);
                *reinterpret_cast<uint32_t*>(cbh + dst + 2 * i) = hi;
                *reinterpret_cast<uint32_t*>(cbl + dst + 2 * i) = lo;
            }
        } else {
#pragma unroll
            for (int i = 0; i < 14; i++) os[(base0 + i) * 56 + oo] = acc[i];
            __syncthreads();
            const int p0 = tid * 14;
            const long dst = (long)n * SH + (long)(64 + c) * HWc + p0;
#pragma unroll
            for (int i = 0; i < 7; i++) {
                uint32_t hi, lo;
                split_fp2(os[p0 + 2 * i], os[p0 + 2 * i + 1], hi, lo);
                *reinterpret_cast<uint32_t*>(cbh + dst + 2 * i) = hi;
                *reinterpret_cast<uint32_t*>(cbl + dst + 2 * i) = lo;
            }
        }
    } else {
        // ======================= depthwise + mean =======================
        float* xs = sm;              // [62][62]
        float* red = sm + 3844;
        const int c = blockIdx.x - 128;

        for (int i = tid; i < 3844; i += 224) xs[i] = 0.f;
        __syncthreads();
        const long yb = (long)n * SF + (long)(128 + c) * HWc;
        for (int i = tid; i < HWc; i += 224) {
            const int h = i / 56;
            xs[(3 + h) * 62 + 3 + (i - h * 56)] = __half2float(yh[yb + i]) + __half2float(yl[yb + i]);
        }
        __syncthreads();

        float kh_[21], kw_[21];
#pragma unroll
        for (int i = 0; i < 21; i++) { kh_[i] = __ldg(&dwh[c * 21 + i]); kw_[i] = __ldg(&dww[c * 21 + i]); }

        const int w = tid % 56;
        const int r0 = (tid / 56) * 14;

        float R[3][7], V[7][3];
#pragma unroll
        for (int a = 0; a < 3; a++)
#pragma unroll
            for (int b = 0; b < 7; b++) R[a][b] = xs[(2 + r0 + a) * 62 + w + b];
#pragma unroll
        for (int a = 0; a < 7; a++)
#pragma unroll
            for (int b = 0; b < 3; b++) V[a][b] = xs[(r0 + a) * 62 + 2 + w + b];

        float lsum = 0.f;
        __half* dh = (__half*)g_x2h4 + (long)n * SH + (long)c * HWc + w;
        __half* dv = (__half*)g_x2w4 + (long)n * SH + (long)c * HWc + w;

#pragma unroll
        for (int j = 0; j < 14; j++) {
            float vh = 0.f, vw = 0.f;
#pragma unroll
            for (int a = 0; a < 3; a++)
#pragma unroll
                for (int b = 0; b < 7; b++)
                    vh += kh_[a * 7 + b] * R[(j + a) % 3][b];
#pragma unroll
            for (int a = 0; a < 7; a++)
#pragma unroll
                for (int b = 0; b < 3; b++)
                    vw += kw_[a * 3 + b] * V[(j + a) % 7][b];
            const float cen = R[(j + 1) % 3][3];
            dh[(r0 + j) * 56] = __float2half_rn(vh);
            dv[(r0 + j) * 56] = __float2half_rn(vw);
            lsum += vh + vw + cen;
            if (j < 13) {
#pragma unroll
                for (int b = 0; b < 7; b++) R[j % 3][b] = xs[(2 + r0 + j + 3) * 62 + w + b];
#pragma unroll
                for (int b = 0; b < 3; b++) V[j % 7][b] = xs[(r0 + j + 7) * 62 + 2 + w + b];
            }
        }

#pragma unroll
        for (int off = 16; off; off >>= 1) lsum += __shfl_down_sync(0xffffffffu, lsum, off);
        if ((tid & 31) == 0) red[tid >> 5] = lsum;
        __syncthreads();
        if (tid == 0) {
            float s = 0.f;
#pragma unroll
            for (int i = 0; i < 7; i++) s += red[i];
            g_att[n * 128 + c] = s * (1.0f / HWc);
        }
    }
}

// ---------------------------------------------------------------------------
// Tiny attention MLP (unchanged).
// ---------------------------------------------------------------------------
__global__ __launch_bounds__(128)
void att_k(const float* __restrict__ w1, const float* __restrict__ b1,
           const float* __restrict__ w2, const float* __restrict__ b2)
{
    __shared__ float satt[128];
    __shared__ float shid[64];
    const int n = blockIdx.x, tid = threadIdx.x;
    satt[tid] = g_att[n * 128 + tid];
    __syncthreads();
    if (tid < 64) {
        float acc = b1[tid];
        for (int c = 0; c < 128; c++) acc += satt[c] * w1[tid * 128 + c];
        shid[tid] = gelu_f(acc);
    }
    __syncthreads();
    float v[3];
#pragma unroll
    for (int k = 0; k < 3; k++) {
        float acc = b2[tid * 3 + k];
        for (int h = 0; h < 64; h++) acc += shid[h] * w2[(tid * 3 + k) * 64 + h];
        v[k] = acc;
    }
    const float m = fmaxf(v[0], fmaxf(v[1], v[2]));
    const float e0 = expf(v[0] - m), e1 = expf(v[1] - m), e2 = expf(v[2] - m);
    const float s = e0 + e1 + e2;
    g_a[n * 384 + tid * 3 + 0] = e0 / s;
    g_a[n * 384 + tid * 3 + 1] = e1 / s;
    g_a[n * 384 + tid * 3 + 2] = e2 / s;
}

// ---------------------------------------------------------------------------
extern "C" void kernel_launch(void* const* d_in, const int* in_sizes, int n_in,
                              void* d_out, int out_size)
{
    const float* x      = (const float*)d_in[0];
    const float* mlp_w  = (const float*)d_in[1];
    const float* mlp_b  = (const float*)d_in[2];
    const float* bn1_g  = (const float*)d_in[3];
    const float* bn1_b  = (const float*)d_in[4];
    const float* bn1_m  = (const float*)d_in[5];
    const float* bn1_v  = (const float*)d_in[6];
    const float* pos_h  = (const float*)d_in[7];
    const float* pos_w  = (const float*)d_in[8];
    const float* pjh_w  = (const float*)d_in[9];
    const float* pjh_b  = (const float*)d_in[10];
    const float* pjw_w  = (const float*)d_in[11];
    const float* pjw_b  = (const float*)d_in[12];
    const float* fuse_h = (const float*)d_in[13];
    const float* bn2_g  = (const float*)d_in[14];
    const float* bn2_b  = (const float*)d_in[15];
    const float* bn2_m  = (const float*)d_in[16];
    const float* bn2_v  = (const float*)d_in[17];
    const float* fuse_w = (const float*)d_in[18];
    const float* fch_w  = (const float*)d_in[19];
    const float* fcw_w  = (const float*)d_in[20];
    const float* rw_w1  = (const float*)d_in[21];
    const float* rw_b1  = (const float*)d_in[22];
    const float* rw_w2  = (const float*)d_in[23];
    const float* rw_b2  = (const float*)d_in[24];
    const float* fout_w = (const float*)d_in[25];

    float *ap;
    void *ybh, *ybl, *cbh, *cbl, *u1h, *u1l, *x2hp, *x2wp, *wfp;
    cudaGetSymbolAddress((void**)&ap, g_a);
    cudaGetSymbolAddress(&ybh, g_ybh4);
    cudaGetSymbolAddress(&ybl, g_ybl4);
    cudaGetSymbolAddress(&cbh, g_cbh4);
    cudaGetSymbolAddress(&cbl, g_cbl4);
    cudaGetSymbolAddress(&u1h, g_u1h4);
    cudaGetSymbolAddress(&u1l, g_u1l4);
    cudaGetSymbolAddress(&x2hp, g_x2h4);
    cudaGetSymbolAddress(&x2wp, g_x2w4);
    cudaGetSymbolAddress(&wfp, g_wf4);

    const __half* WF = (const __half*)wfp;

    cudaFuncSetAttribute(tc_gemm<1,1,2>, cudaFuncAttributeMaxDynamicSharedMemorySize, SMEM_GEMM);
    cudaFuncSetAttribute(tc_gemm<2,0,0>, cudaFuncAttributeMaxDynamicSharedMemorySize, SMEM_GEMM);
    cudaFuncSetAttribute(tc_g23, cudaFuncAttributeMaxDynamicSharedMemorySize, SMEM_G23);

    wprep_k<<<dim3(6, 8), 256>>>(mlp_w, fuse_h, fuse_w, fout_w);

    // GEMM1: y = gelu(bn(x@mlp_w + b)), ch<128 += pos_h ; fp16 hi/lo out
    tc_gemm<1,1,2><<<dim3(2, NPB), 256, SMEM_GEMM>>>(
        WF, nullptr, nullptr, 0, nullptr, nullptr, 0,
        x, SF, nullptr, 0,
        (__half*)ybh, (__half*)ybl, SF,
        mlp_b, bn1_g, bn1_b, bn1_m, bn1_v, pos_h, nullptr, nullptr, nullptr);

    // merged strips + depthwise (one launch, better wave packing)
    sd_k<<<dim3(256, 16), 224>>>(pjh_w, pjh_b, pjw_w, pjw_b, fch_w, fcw_w,
        (const __half*)ybh, (const __half*)ybl);
    att_k<<<16, 128>>>(rw_w1, rw_b1, rw_w2, rw_b2);

    // Fused GEMM2+3 -> u1 (fp16 hi/lo)
    tc_g23<<<dim3(1, NPB), 256, SMEM_G23>>>(
        WF + 2L * 40960, WF + 3L * 40960,
        (const __half*)cbh, (const __half*)cbl,
        (const __half*)ybh, (const __half*)ybl,
        (__half*)u1h, (__half*)u1l,
        bn2_g, bn2_b, bn2_m, bn2_v, pos_w);

    // GEMM4 (2-term): out = concat[u1, a0*x2h + a1*x2w + a2*y2]@fuse_out
    tc_gemm<2,0,0><<<dim3(2, NPB), 256, SMEM_GEMM>>>(
        WF + 4L * 40960,
        (const __half*)u1h, (const __half*)u1l, SH,
        (const __half*)ybh + 128L * HWc, (const __half*)ybl + 128L * HWc, SF,
        nullptr, 0, (float*)d_out, SF,
        nullptr, nullptr, 0,
        nullptr, nullptr, nullptr, nullptr, nullptr, nullptr,
        (const __half*)x2hp, (const __half*)x2wp, ap);
}

// round 15
// speedup vs baseline: 1.1063x; 1.0358x over previous
#include <cuda_runtime.h>
#include <cuda_fp16.h>
#include <math.h>
#include <stdint.h>

#define Nn   16
#define Cc   256
#define C1c  128
#define HWc  3136
#define EPSf 1e-5f
#define PBI  25
#define NPB  (Nn*PBI)
#define SF   (Cc*HWc)
#define SH   (C1c*HWc)

// ---------------- scratch (device globals; no allocations) ----------------
__device__ float g_att[Nn*C1c];
__device__ float g_a  [Nn*C1c*3];

__device__ uint4 g_ybh4[(Nn*Cc *HWc + 256) / 8];
__device__ uint4 g_ybl4[(Nn*Cc *HWc + 256) / 8];
__device__ uint4 g_cbh4[(Nn*C1c*HWc + 256) / 8];
__device__ uint4 g_cbl4[(Nn*C1c*HWc + 256) / 8];
__device__ uint4 g_u1h4[(Nn*C1c*HWc + 256) / 8];
__device__ uint4 g_u1l4[(Nn*C1c*HWc + 256) / 8];
__device__ uint4 g_x2h4[(Nn*C1c*HWc + 256) / 8];
__device__ uint4 g_x2w4[(Nn*C1c*HWc + 256) / 8];
// prepped weights (fp16): 6 slots x 8 chunks x [128 n][40 halves]
__device__ uint4 g_wf4[6 * 40960 / 8];

__device__ __forceinline__ float gelu_f(float x) {
    return 0.5f * x * (1.0f + erff(x * 0.7071067811865476f));
}
__device__ __forceinline__ uint32_t smem_to_u32(const void* p) {
    uint32_t a;
    asm("{ .reg .u64 t; cvta.to.shared.u64 t, %1; cvt.u32.u64 %0, t; }" : "=r"(a) : "l"(p));
    return a;
}
__device__ __forceinline__ void split_fp2(float x0, float x1, uint32_t& hi, uint32_t& lo) {
    const __half h0 = __float2half_rn(x0);
    const __half h1 = __float2half_rn(x1);
    const __half l0 = __float2half_rn(x0 - __half2float(h0));
    const __half l1 = __float2half_rn(x1 - __half2float(h1));
    hi = (uint32_t)__half_as_ushort(h0) | ((uint32_t)__half_as_ushort(h1) << 16);
    lo = (uint32_t)__half_as_ushort(l0) | ((uint32_t)__half_as_ushort(l1) << 16);
}
__device__ __forceinline__ uint32_t pack_fp2(float x0, float x1) {
    const __half h0 = __float2half_rn(x0);
    const __half h1 = __float2half_rn(x1);
    return (uint32_t)__half_as_ushort(h0) | ((uint32_t)__half_as_ushort(h1) << 16);
}
__device__ __forceinline__ void ldsm4(uint32_t (&r)[4], uint32_t addr) {
    asm volatile("ldmatrix.sync.aligned.m8n8.x4.shared.b16 {%0,%1,%2,%3}, [%4];"
        : "=r"(r[0]), "=r"(r[1]), "=r"(r[2]), "=r"(r[3]) : "r"(addr));
}
__device__ __forceinline__ void ldsm4t(uint32_t (&r)[4], uint32_t addr) {
    asm volatile("ldmatrix.sync.aligned.m8n8.x4.trans.shared.b16 {%0,%1,%2,%3}, [%4];"
        : "=r"(r[0]), "=r"(r[1]), "=r"(r[2]), "=r"(r[3]) : "r"(addr));
}
__device__ __forceinline__ void mma16816(float (&c)[4], const uint32_t (&a)[4], uint32_t b0, uint32_t b1) {
    asm volatile("mma.sync.aligned.m16n8k16.row.col.f32.f16.f16.f32 "
        "{%0,%1,%2,%3}, {%4,%5,%6,%7}, {%8,%9}, {%0,%1,%2,%3};"
        : "+f"(c[0]), "+f"(c[1]), "+f"(c[2]), "+f"(c[3])
        : "r"(a[0]), "r"(a[1]), "r"(a[2]), "r"(a[3]), "r"(b0), "r"(b1));
}
#define CP16(dst, src) asm volatile("cp.async.cg.shared.global [%0], [%1], 16;" :: "r"(dst), "l"(src))
#define CP_COMMIT()    asm volatile("cp.async.commit_group;" ::: "memory")

// ---------------------------------------------------------------------------
// Weight prep (unchanged).
// ---------------------------------------------------------------------------
__global__ __launch_bounds__(256)
void wprep_k(const float* __restrict__ mlp_w, const float* __restrict__ fuse_h,
             const float* __restrict__ fuse_w, const float* __restrict__ fout_w)
{
    const int slot = blockIdx.x, kc = blockIdx.y, tid = threadIdx.x;
    const float* W; int o0;
    switch (slot) {
        case 0: W = mlp_w;  o0 = 0;   break;
        case 1: W = mlp_w;  o0 = 128; break;
        case 2: W = fuse_h; o0 = 0;   break;
        case 3: W = fuse_w; o0 = 0;   break;
        case 4: W = fout_w; o0 = 0;   break;
        default:W = fout_w; o0 = 128; break;
    }
    const int n = tid >> 1;
    const int kh = (tid & 1) * 16;
    const float* src = W + (long)(o0 + n) * 256 + kc * 32 + kh;
    uint32_t hp[8];
#pragma unroll
    for (int j = 0; j < 8; j++) {
        const float2 v = *reinterpret_cast<const float2*>(src + 2 * j);
        hp[j] = pack_fp2(v.x, v.y);
    }
    __half* dh = (__half*)g_wf4 + (long)slot * 40960 + kc * 5120 + n * 40 + kh;
    *reinterpret_cast<uint4*>(dh)     = *reinterpret_cast<uint4*>(&hp[0]);
    *reinterpret_cast<uint4*>(dh + 8) = *reinterpret_cast<uint4*>(&hp[4]);
    if (tid < 128) {
        const uint4 z = {0, 0, 0, 0};
        *reinterpret_cast<uint4*>((__half*)g_wf4 + (long)slot * 40960 + kc * 5120 + tid * 40 + 32) = z;
    }
}

// ---------------------------------------------------------------------------
// Generic GEMM (exact R12/R14 geometry).
// ---------------------------------------------------------------------------
#define STG 27648
#define ALB 8704
#define BHB 17408
#define SMEM_GEMM 67584

template<int APATH, int EPI, int OUT>
__global__ __launch_bounds__(256, 2)
void tc_gemm(const __half* __restrict__ wf,
             const __half* __restrict__ s1h, const __half* __restrict__ s1l, int str1,
             const __half* __restrict__ s2h, const __half* __restrict__ s2l, int str2,
             const float* __restrict__ xin, int strX,
             float* __restrict__ out, int strO,
             __half* __restrict__ obh, __half* __restrict__ obl, int strOB,
             const float* __restrict__ e_bias,
             const float* __restrict__ e_g, const float* __restrict__ e_b,
             const float* __restrict__ e_m, const float* __restrict__ e_v,
             const float* __restrict__ e_pos,
             const __half* __restrict__ cH, const __half* __restrict__ cW,
             const float* __restrict__ cA)
{
    extern __shared__ __align__(16) char smc[];
    const uint32_t sm_sa = smem_to_u32(smc);

    const int tid = threadIdx.x;
    const int wid = tid >> 5;
    const int lane = tid & 31;
    const int o0 = blockIdx.x * 128;
    const int nimg = blockIdx.y / PBI;
    const int pix0 = (blockIdx.y % PBI) * 128;
    const int warp_m = (wid & 3) * 32;
    const int warp_n = (wid >> 2) * 64;

    const __half* wfB = wf + (long)blockIdx.x * 40960;

    const int pix2 = tid & 63;
    const int rgrp = tid >> 6;
    int p0 = pix0 + 2 * pix2;
    if (p0 > HWc - 2) p0 = HWc - 2;

    auto issue = [&](int kc, int buf) {
        const uint32_t base = sm_sa + buf * STG;
        char* bp = smc + buf * STG;
        if (APATH == 1) {
            const float* src = xin + (long)nimg * strX + p0;
#pragma unroll
            for (int j = 0; j < 8; j++) {
                const int r = rgrp + 4 * j;
                const float2 v = *reinterpret_cast<const float2*>(src + (long)(kc * 32 + r) * HWc);
                uint32_t hi, lo;
                split_fp2(v.x, v.y, hi, lo);
                *reinterpret_cast<uint32_t*>(bp + r * 272 + pix2 * 4) = hi;
                *reinterpret_cast<uint32_t*>(bp + ALB + r * 272 + pix2 * 4) = lo;
            }
        } else if (kc < 4) {
            const long chb = (long)nimg * str1 + (long)(kc * 32) * HWc + pix0;
#pragma unroll
            for (int it = 0; it < 2; it++) {
                const int idx = tid + it * 256;
                const int row = idx >> 4, seg = idx & 15;
                const char* gh = (const char*)(s1h + chb + (long)row * HWc) + seg * 16;
                const char* gl = (const char*)(s1l + chb + (long)row * HWc) + seg * 16;
                CP16(base + row * 272 + seg * 16, gh);
                CP16(base + ALB + row * 272 + seg * 16, gl);
            }
        } else {
            const long ib = (long)nimg * SH + p0;
            const __half* pH = cH + ib;
            const __half* pW = cW + ib;
            const __half* pXh = s2h + (long)nimg * str2 + p0;
            const __half* pXl = s2l + (long)nimg * str2 + p0;
            const float* aB = cA + nimg * 384;
#pragma unroll
            for (int j = 0; j < 8; j++) {
                const int r = rgrp + 4 * j;
                const int cc = (kc - 4) * 32 + r;
                const float a0 = aB[cc * 3], a1 = aB[cc * 3 + 1], a2 = aB[cc * 3 + 2];
                const __half2 vh2 = *reinterpret_cast<const __half2*>(pH + (long)cc * HWc);
                const __half2 vw2 = *reinterpret_cast<const __half2*>(pW + (long)cc * HWc);
                const __half2 xh2 = *reinterpret_cast<const __half2*>(pXh + (long)cc * HWc);
                const __half2 xl2 = *reinterpret_cast<const __half2*>(pXl + (long)cc * HWc);
                float2 v;
                v.x = a0 * __half2float(vh2.x) + a1 * __half2float(vw2.x)
                    + a2 * (__half2float(xh2.x) + __half2float(xl2.x));
                v.y = a0 * __half2float(vh2.y) + a1 * __half2float(vw2.y)
                    + a2 * (__half2float(xh2.y) + __half2float(xl2.y));
                uint32_t hi, lo;
                split_fp2(v.x, v.y, hi, lo);
                *reinterpret_cast<uint32_t*>(bp + r * 272 + pix2 * 4) = hi;
                *reinterpret_cast<uint32_t*>(bp + ALB + r * 272 + pix2 * 4) = lo;
            }
        }
        const char* wsrc = (const char*)(wfB + kc * 5120);
#pragma unroll
        for (int it = 0; it < 3; it++) {
            const int i = tid + it * 256;
            if (i < 640) CP16(base + BHB + i * 16, wsrc + i * 16);
        }
    };

    const int a_kr = (lane & 7) + ((lane & 16) >> 1);
    const int a_mc = (lane & 8);
    const int b_nr = (lane & 7) + ((lane & 16) >> 1);
    const int b_kc = (lane & 8);

    float acc[2][8][4];
#pragma unroll
    for (int mt = 0; mt < 2; mt++)
#pragma unroll
        for (int nf = 0; nf < 8; nf++)
#pragma unroll
            for (int j = 0; j < 4; j++) acc[mt][nf][j] = 0.f;

    issue(0, 0);
    CP_COMMIT();

#pragma unroll 1
    for (int kc = 0; kc < 8; kc++) {
        if (kc < 7) { issue(kc + 1, (kc + 1) & 1); CP_COMMIT(); }
        if (kc < 7) asm volatile("cp.async.wait_group 1;" ::: "memory");
        else        asm volatile("cp.async.wait_group 0;" ::: "memory");
        __syncthreads();

        const uint32_t base = sm_sa + (kc & 1) * STG;
#pragma unroll
        for (int ks = 0; ks < 2; ks++) {
            const int k0 = ks * 16;
            uint32_t ah[2][4], al[2][4];
#pragma unroll
            for (int half = 0; half < 2; half++) {
                const uint32_t ea = (uint32_t)((k0 + a_kr) * 136 + warp_m + half * 16 + a_mc) * 2;
                ldsm4t(ah[half], base + ea);
                ldsm4t(al[half], base + ALB + ea);
            }
#pragma unroll
            for (int ng = 0; ng < 4; ng++) {
                const uint32_t eb = (uint32_t)((warp_n + ng * 16 + b_nr) * 40 + k0 + b_kc) * 2;
                uint32_t th[4];
                ldsm4(th, base + BHB + eb);
#pragma unroll
                for (int mt = 0; mt < 2; mt++) {
                    mma16816(acc[mt][2 * ng],     ah[mt], th[0], th[1]);
                    mma16816(acc[mt][2 * ng],     al[mt], th[0], th[1]);
                    mma16816(acc[mt][2 * ng + 1], ah[mt], th[2], th[3]);
                    mma16816(acc[mt][2 * ng + 1], al[mt], th[2], th[3]);
                }
            }
        }
        __syncthreads();
    }

    // ---- epilogue ----
    float* O = reinterpret_cast<float*>(smc);
#pragma unroll
    for (int mt = 0; mt < 2; mt++)
#pragma unroll
        for (int nf = 0; nf < 8; nf++) {
            const int n = warp_n + nf * 8 + (lane & 3) * 2;
            const int m = warp_m + mt * 16 + (lane >> 2);
            O[n * 132 + m]           = acc[mt][nf][0];
            O[(n + 1) * 132 + m]     = acc[mt][nf][1];
            O[n * 132 + m + 8]       = acc[mt][nf][2];
            O[(n + 1) * 132 + m + 8] = acc[mt][nf][3];
        }
    __syncthreads();

    {
        const int m0 = lane * 4;
        const int hw0 = pix0 + m0;
        const bool pvalid = (hw0 < HWc);
        int rel[4] = {0, 0, 0, 0};
        if (pvalid && EPI != 0) {
#pragma unroll
            for (int j = 0; j < 4; j++) {
                const int hwj = hw0 + j;
                const int h = hwj / 56;
                rel[j] = (hwj - h * 56) - h + 56;
            }
        }
        if (pvalid) {
#pragma unroll
            for (int r = 0; r < 16; r++) {
                const int n = wid * 16 + r;
                const int o = o0 + n;
                const float4 v = *reinterpret_cast<const float4*>(&O[n * 132 + m0]);
                float vv[4] = {v.x, v.y, v.z, v.w};
                if (EPI == 1) {
                    const float s = __ldg(&e_g[o]) * rsqrtf(__ldg(&e_v[o]) + EPSf);
                    const float t = __ldg(&e_b[o]) - __ldg(&e_m[o]) * s;
                    const float bb = __ldg(&e_bias[o]);
#pragma unroll
                    for (int j = 0; j < 4; j++) {
                        float u = gelu_f((vv[j] + bb) * s + t);
                        if (o < 128) u += __ldg(&e_pos[rel[j] * 128 + o]);
                        vv[j] = u;
                    }
                }
                if (OUT != 2) {
                    float4 ov;
                    ov.x = vv[0]; ov.y = vv[1]; ov.z = vv[2]; ov.w = vv[3];
                    *reinterpret_cast<float4*>(&out[(long)nimg * strO + (long)o * HWc + hw0]) = ov;
                }
                if (OUT != 0) {
                    uint32_t h0, l0, h1, l1;
                    split_fp2(vv[0], vv[1], h0, l0);
                    split_fp2(vv[2], vv[3], h1, l1);
                    const long eoff = (long)nimg * strOB + (long)o * HWc + hw0;
                    *reinterpret_cast<uint2*>(obh + eoff) = make_uint2(h0, h1);
                    *reinterpret_cast<uint2*>(obl + eoff) = make_uint2(l0, l1);
                }
            }
        }
    }
}

// ---------------------------------------------------------------------------
// Fused GEMM2+GEMM3 (unchanged from R14).
// ---------------------------------------------------------------------------
#define T_OFF 55296
#define SMEM_G23 90112

__global__ __launch_bounds__(256, 2)
void tc_g23(const __half* __restrict__ wf2, const __half* __restrict__ wf3,
            const __half* __restrict__ s1h, const __half* __restrict__ s1l,
            const __half* __restrict__ yh, const __half* __restrict__ yl,
            __half* __restrict__ obh, __half* __restrict__ obl,
            const float* __restrict__ e_g, const float* __restrict__ e_b,
            const float* __restrict__ e_m, const float* __restrict__ e_v,
            const float* __restrict__ e_pos)
{
    extern __shared__ __align__(16) char smc[];
    const uint32_t sm_sa = smem_to_u32(smc);

    const int tid = threadIdx.x;
    const int wid = tid >> 5;
    const int lane = tid & 31;
    const int nimg = blockIdx.y / PBI;
    const int pix0 = (blockIdx.y % PBI) * 128;
    const int warp_m = (wid & 3) * 32;
    const int warp_n = (wid >> 2) * 64;

    const int a_kr = (lane & 7) + ((lane & 16) >> 1);
    const int a_mc = (lane & 8);
    const int b_nr = (lane & 7) + ((lane & 16) >> 1);
    const int b_kc = (lane & 8);

    auto stageA = [&](const __half* sh, const __half* sl, int str, int c0, uint32_t base) {
        const long chb = (long)nimg * str + (long)c0 * HWc + pix0;
#pragma unroll
        for (int it = 0; it < 2; it++) {
            const int idx = tid + it * 256;
            const int row = idx >> 4, seg = idx & 15;
            const char* gh = (const char*)(sh + chb + (long)row * HWc) + seg * 16;
            const char* gl = (const char*)(sl + chb + (long)row * HWc) + seg * 16;
            CP16(base + row * 272 + seg * 16, gh);
            CP16(base + ALB + row * 272 + seg * 16, gl);
        }
    };
    auto stageB = [&](const __half* wf, int kc, uint32_t base) {
        const char* wsrc = (const char*)(wf + kc * 5120);
#pragma unroll
        for (int it = 0; it < 3; it++) {
            const int i = tid + it * 256;
            if (i < 640) CP16(base + BHB + i * 16, wsrc + i * 16);
        }
    };

    float acc[2][8][4];
#pragma unroll
    for (int mt = 0; mt < 2; mt++)
#pragma unroll
        for (int nf = 0; nf < 8; nf++)
#pragma unroll
            for (int j = 0; j < 4; j++) acc[mt][nf][j] = 0.f;

    auto issue1 = [&](int kc, int buf) {
        const uint32_t base = sm_sa + buf * STG;
        if (kc < 4) stageA(s1h, s1l, SH, kc * 32, base);
        else        stageA(yh,  yl,  SF, (kc - 4) * 32, base);
        stageB(wf2, kc, base);
    };

    issue1(0, 0);
    CP_COMMIT();

#pragma unroll 1
    for (int kc = 0; kc < 8; kc++) {
        if (kc < 7) { issue1(kc + 1, (kc + 1) & 1); CP_COMMIT(); }
        if (kc < 7) asm volatile("cp.async.wait_group 1;" ::: "memory");
        else        asm volatile("cp.async.wait_group 0;" ::: "memory");
        __syncthreads();

        const uint32_t base = sm_sa + (kc & 1) * STG;
#pragma unroll
        for (int ks = 0; ks < 2; ks++) {
            const int k0 = ks * 16;
            uint32_t ah[2][4], al[2][4];
#pragma unroll
            for (int half = 0; half < 2; half++) {
                const uint32_t ea = (uint32_t)((k0 + a_kr) * 136 + warp_m + half * 16 + a_mc) * 2;
                ldsm4t(ah[half], base + ea);
                ldsm4t(al[half], base + ALB + ea);
            }
#pragma unroll
            for (int ng = 0; ng < 4; ng++) {
                const uint32_t eb = (uint32_t)((warp_n + ng * 16 + b_nr) * 40 + k0 + b_kc) * 2;
                uint32_t th[4];
                ldsm4(th, base + BHB + eb);
#pragma unroll
                for (int mt = 0; mt < 2; mt++) {
                    mma16816(acc[mt][2 * ng],     ah[mt], th[0], th[1]);
                    mma16816(acc[mt][2 * ng],     al[mt], th[0], th[1]);
                    mma16816(acc[mt][2 * ng + 1], ah[mt], th[2], th[3]);
                    mma16816(acc[mt][2 * ng + 1], al[mt], th[2], th[3]);
                }
            }
        }
        __syncthreads();
    }

    stageB(wf3, 0, sm_sa);
    CP_COMMIT();

    {
        __half* T = reinterpret_cast<__half*>(smc + T_OFF);
#pragma unroll
        for (int nf = 0; nf < 8; nf++) {
            const int n0 = warp_n + nf * 8 + (lane & 3) * 2;
            const float sA = __ldg(&e_g[n0]) * rsqrtf(__ldg(&e_v[n0]) + EPSf);
            const float tA = __ldg(&e_b[n0]) - __ldg(&e_m[n0]) * sA;
            const float sB = __ldg(&e_g[n0 + 1]) * rsqrtf(__ldg(&e_v[n0 + 1]) + EPSf);
            const float tB = __ldg(&e_b[n0 + 1]) - __ldg(&e_m[n0 + 1]) * sB;
#pragma unroll
            for (int mt = 0; mt < 2; mt++) {
                const int m = warp_m + mt * 16 + (lane >> 2);
                int hw = pix0 + m; if (hw > HWc - 1) hw = HWc - 1;
                int h = hw / 56;
                const int rel0 = (hw - h * 56) - h + 56;
                int hw8 = pix0 + m + 8; if (hw8 > HWc - 1) hw8 = HWc - 1;
                h = hw8 / 56;
                const int rel8 = (hw8 - h * 56) - h + 56;
                const float v0 = gelu_f(acc[mt][nf][0] * sA + tA) + __ldg(&e_pos[rel0 * 128 + n0]);
                const float v1 = gelu_f(acc[mt][nf][1] * sB + tB) + __ldg(&e_pos[rel0 * 128 + n0 + 1]);
                const float v2 = gelu_f(acc[mt][nf][2] * sA + tA) + __ldg(&e_pos[rel8 * 128 + n0]);
                const float v3 = gelu_f(acc[mt][nf][3] * sB + tB) + __ldg(&e_pos[rel8 * 128 + n0 + 1]);
                T[n0 * 136 + m]            = __float2half_rn(v0);
                T[(n0 + 1) * 136 + m]      = __float2half_rn(v1);
                T[n0 * 136 + m + 8]        = __float2half_rn(v2);
                T[(n0 + 1) * 136 + m + 8]  = __float2half_rn(v3);
            }
        }
    }
    __syncthreads();

#pragma unroll
    for (int mt = 0; mt < 2; mt++)
#pragma unroll
        for (int nf = 0; nf < 8; nf++)
#pragma unroll
            for (int j = 0; j < 4; j++) acc[mt][nf][j] = 0.f;

    auto issue2 = [&](int kc, int buf) {
        const uint32_t base = sm_sa + buf * STG;
        if (kc >= 4) stageA(yh + 128L * HWc, yl + 128L * HWc, SF, (kc - 4) * 32, base);
        stageB(wf3, kc, base);
    };

#pragma unroll 1
    for (int kc = 0; kc < 8; kc++) {
        if (kc < 7) { issue2(kc + 1, (kc + 1) & 1); CP_COMMIT(); }
        if (kc < 7) asm volatile("cp.async.wait_group 1;" ::: "memory");
        else        asm volatile("cp.async.wait_group 0;" ::: "memory");
        __syncthreads();

        const uint32_t base = sm_sa + (kc & 1) * STG;
        if (kc < 4) {
#pragma unroll
            for (int ks = 0; ks < 2; ks++) {
                const int k0 = ks * 16;
                uint32_t ah[2][4];
#pragma unroll
                for (int half = 0; half < 2; half++) {
                    const uint32_t ea = (uint32_t)((kc * 32 + k0 + a_kr) * 136 + warp_m + half * 16 + a_mc) * 2;
                    ldsm4t(ah[half], sm_sa + T_OFF + ea);
                }
#pragma unroll
                for (int ng = 0; ng < 4; ng++) {
                    const uint32_t eb = (uint32_t)((warp_n + ng * 16 + b_nr) * 40 + k0 + b_kc) * 2;
                    uint32_t th[4];
                    ldsm4(th, base + BHB + eb);
#pragma unroll
                    for (int mt = 0; mt < 2; mt++) {
                        mma16816(acc[mt][2 * ng],     ah[mt], th[0], th[1]);
                        mma16816(acc[mt][2 * ng + 1], ah[mt], th[2], th[3]);
                    }
                }
            }
        } else {
#pragma unroll
            for (int ks = 0; ks < 2; ks++) {
                const int k0 = ks * 16;
                uint32_t ah[2][4], al[2][4];
#pragma unroll
                for (int half = 0; half < 2; half++) {
                    const uint32_t ea = (uint32_t)((k0 + a_kr) * 136 + warp_m + half * 16 + a_mc) * 2;
                    ldsm4t(ah[half], base + ea);
                    ldsm4t(al[half], base + ALB + ea);
                }
#pragma unroll
                for (int ng = 0; ng < 4; ng++) {
                    const uint32_t eb = (uint32_t)((warp_n + ng * 16 + b_nr) * 40 + k0 + b_kc) * 2;
                    uint32_t th[4];
                    ldsm4(th, base + BHB + eb);
#pragma unroll
                    for (int mt = 0; mt < 2; mt++) {
                        mma16816(acc[mt][2 * ng],     ah[mt], th[0], th[1]);
                        mma16816(acc[mt][2 * ng],     al[mt], th[0], th[1]);
                        mma16816(acc[mt][2 * ng + 1], ah[mt], th[2], th[3]);
                        mma16816(acc[mt][2 * ng + 1], al[mt], th[2], th[3]);
                    }
                }
            }
        }
        __syncthreads();
    }

    float* O = reinterpret_cast<float*>(smc);
#pragma unroll
    for (int mt = 0; mt < 2; mt++)
#pragma unroll
        for (int nf = 0; nf < 8; nf++) {
            const int n = warp_n + nf * 8 + (lane & 3) * 2;
            const int m = warp_m + mt * 16 + (lane >> 2);
            O[n * 132 + m]           = acc[mt][nf][0];
            O[(n + 1) * 132 + m]     = acc[mt][nf][1];
            O[n * 132 + m + 8]       = acc[mt][nf][2];
            O[(n + 1) * 132 + m + 8] = acc[mt][nf][3];
        }
    __syncthreads();

    {
        const int m0 = lane * 4;
        const int hw0 = pix0 + m0;
        if (hw0 < HWc) {
#pragma unroll
            for (int r = 0; r < 16; r++) {
                const int n = wid * 16 + r;
                const float4 v = *reinterpret_cast<const float4*>(&O[n * 132 + m0]);
                uint32_t h0, l0, h1, l1;
                split_fp2(v.x, v.y, h0, l0);
                split_fp2(v.z, v.w, h1, l1);
                const long eoff = (long)nimg * SH + (long)n * HWc + hw0;
                *reinterpret_cast<uint2*>(obh + eoff) = make_uint2(h0, h1);
                *reinterpret_cast<uint2*>(obl + eoff) = make_uint2(l0, l1);
            }
        }
    }
}

// ---------------------------------------------------------------------------
// Merged strip + depthwise kernel (unchanged from R14).
// ---------------------------------------------------------------------------
__global__ __launch_bounds__(224)
void sd_k(const float* __restrict__ Wh, const float* __restrict__ bh,
          const float* __restrict__ Ww, const float* __restrict__ bw,
          const float* __restrict__ dwh, const float* __restrict__ dww,
          const __half* __restrict__ yh, const __half* __restrict__ yl)
{
    __shared__ float sm[6500];
    const int n = blockIdx.y;
    const int tid = threadIdx.x;

    if (blockIdx.x < 128) {
        float* xs = sm;
        float* os = sm + 3364;
        const bool WVAR = blockIdx.x >= 64;
        const int c = blockIdx.x & 63;
        const float* Wg = WVAR ? Ww : Wh;
        const float* bias = WVAR ? bw : bh;

        for (int i = tid; i < 3364; i += 224) xs[i] = 0.f;
        __syncthreads();
        {
            const long yb = (long)n * SF + (long)((WVAR ? 64 : 0) + c) * HWc;
            for (int i = tid; i < HWc; i += 224) {
                const float v = __half2float(yh[yb + i]) + __half2float(yl[yb + i]);
                const int h = i / 56, w = i - h * 56;
                if (WVAR) xs[(1 + w) * 58 + 1 + h] = v;
                else      xs[(1 + h) * 58 + 1 + w] = v;
            }
        }
        __syncthreads();

        const int oo = tid >> 2;
        const int base0 = (tid & 3) * 14;
        const float* wrow = Wg + ((long)c * 56 + oo) * 168;

        float acc[14];
        const float bval = __ldg(&bias[c * 56 + oo]);
#pragma unroll
        for (int i = 0; i < 14; i++) acc[i] = bval;

        for (int hp = 0; hp < 56; hp++) {
            const float w0 = __ldg(&wrow[hp * 3 + 0]);
            const float w1 = __ldg(&wrow[hp * 3 + 1]);
            const float w2 = __ldg(&wrow[hp * 3 + 2]);
            const float* xr = xs + (1 + hp) * 58 + base0;
            float xv[16];
#pragma unroll
            for (int t = 0; t < 16; t++) xv[t] = xr[t];
#pragma unroll
            for (int i = 0; i < 14; i++) acc[i] += w0 * xv[i] + w1 * xv[i + 1] + w2 * xv[i + 2];
        }

        __half* cbh = (__half*)g_cbh4;
        __half* cbl = (__half*)g_cbl4;

        if (!WVAR) {
            const long dst = (long)n * SH + (long)c * HWc + oo * 56 + base0;
#pragma unroll
            for (int i = 0; i < 7; i++) {
                uint32_t hi, lo;
                split_fp2(acc[2 * i], acc[2 * i + 1], hi, lo);
                *reinterpret_cast<uint32_t*>(cbh + dst + 2 * i) = hi;
                *reinterpret_cast<uint32_t*>(cbl + dst + 2 * i) = lo;
            }
        } else {
#pragma unroll
            for (int i = 0; i < 14; i++) os[(base0 + i) * 56 + oo] = acc[i];
            __syncthreads();
            const int p0 = tid * 14;
            const long dst = (long)n * SH + (long)(64 + c) * HWc + p0;
#pragma unroll
            for (int i = 0; i < 7; i++) {
                uint32_t hi, lo;
                split_fp2(os[p0 + 2 * i], os[p0 + 2 * i + 1], hi, lo);
                *reinterpret_cast<uint32_t*>(cbh + dst + 2 * i) = hi;
                *reinterpret_cast<uint32_t*>(cbl + dst + 2 * i) = lo;
            }
        }
    } else {
        float* xs = sm;
        float* red = sm + 3844;
        const int c = blockIdx.x - 128;

        for (int i = tid; i < 3844; i += 224) xs[i] = 0.f;
        __syncthreads();
        const long yb = (long)n * SF + (long)(128 + c) * HWc;
        for (int i = tid; i < HWc; i += 224) {
            const int h = i / 56;
            xs[(3 + h) * 62 + 3 + (i - h * 56)] = __half2float(yh[yb + i]) + __half2float(yl[yb + i]);
        }
        __syncthreads();

        float kh_[21], kw_[21];
#pragma unroll
        for (int i = 0; i < 21; i++) { kh_[i] = __ldg(&dwh[c * 21 + i]); kw_[i] = __ldg(&dww[c * 21 + i]); }

        const int w = tid % 56;
        const int r0 = (tid / 56) * 14;

        float R[3][7], V[7][3];
#pragma unroll
        for (int a = 0; a < 3; a++)
#pragma unroll
            for (int b = 0; b < 7; b++) R[a][b] = xs[(2 + r0 + a) * 62 + w + b];
#pragma unroll
        for (int a = 0; a < 7; a++)
#pragma unroll
            for (int b = 0; b < 3; b++) V[a][b] = xs[(r0 + a) * 62 + 2 + w + b];

        float lsum = 0.f;
        __half* dh = (__half*)g_x2h4 + (long)n * SH + (long)c * HWc + w;
        __half* dv = (__half*)g_x2w4 + (long)n * SH + (long)c * HWc + w;

#pragma unroll
        for (int j = 0; j < 14; j++) {
            float vh = 0.f, vw = 0.f;
#pragma unroll
            for (int a = 0; a < 3; a++)
#pragma unroll
                for (int b = 0; b < 7; b++)
                    vh += kh_[a * 7 + b] * R[(j + a) % 3][b];
#pragma unroll
            for (int a = 0; a < 7; a++)
#pragma unroll
                for (int b = 0; b < 3; b++)
                    vw += kw_[a * 3 + b] * V[(j + a) % 7][b];
            const float cen = R[(j + 1) % 3][3];
            dh[(r0 + j) * 56] = __float2half_rn(vh);
            dv[(r0 + j) * 56] = __float2half_rn(vw);
            lsum += vh + vw + cen;
            if (j < 13) {
#pragma unroll
                for (int b = 0; b < 7; b++) R[j % 3][b] = xs[(2 + r0 + j + 3) * 62 + w + b];
#pragma unroll
                for (int b = 0; b < 3; b++) V[j % 7][b] = xs[(r0 + j + 7) * 62 + 2 + w + b];
            }
        }

#pragma unroll
        for (int off = 16; off; off >>= 1) lsum += __shfl_down_sync(0xffffffffu, lsum, off);
        if ((tid & 31) == 0) red[tid >> 5] = lsum;
        __syncthreads();
        if (tid == 0) {
            float s = 0.f;
#pragma unroll
            for (int i = 0; i < 7; i++) s += red[i];
            g_att[n * 128 + c] = s * (1.0f / HWc);
        }
    }
}

// ---------------------------------------------------------------------------
// Attention MLP, latency-optimized: 256 threads, coalesced/vectorized loads.
// Phase1: 4 threads per hidden unit + shfl reduce. Phase2: float4 w2 rows.
// ---------------------------------------------------------------------------
__global__ __launch_bounds__(256)
void att_k(const float* __restrict__ w1, const float* __restrict__ b1,
           const float* __restrict__ w2, const float* __restrict__ b2)
{
    __shared__ float satt[128];
    __shared__ float shid[64];
    __shared__ float sv[384];
    const int n = blockIdx.x, tid = threadIdx.x;

    if (tid < 128) satt[tid] = g_att[n * 128 + tid];
    __syncthreads();

    // phase 1: hidden[o] = gelu(b1[o] + sum_c satt[c]*w1[o*128+c])
    {
        const int o = tid >> 2;          // 0..63
        const int part = tid & 3;        // 0..3
        const float* wr = w1 + o * 128 + part * 32;
        const float* sa = satt + part * 32;
        float acc = 0.f;
#pragma unroll
        for (int c = 0; c < 32; c += 4) {
            const float4 wv = *reinterpret_cast<const float4*>(wr + c);
            acc += sa[c] * wv.x + sa[c + 1] * wv.y + sa[c + 2] * wv.z + sa[c + 3] * wv.w;
        }
        acc += __shfl_xor_sync(0xffffffffu, acc, 1);
        acc += __shfl_xor_sync(0xffffffffu, acc, 2);
        if (part == 0) shid[o] = gelu_f(acc + __ldg(&b1[o]));
    }
    __syncthreads();

    // phase 2: sv[idx] = b2[idx] + sum_h shid[h]*w2[idx*64+h]
    for (int idx = tid; idx < 384; idx += 256) {
        const float* wr = w2 + idx * 64;
        float acc = __ldg(&b2[idx]);
#pragma unroll
        for (int h = 0; h < 64; h += 4) {
            const float4 wv = *reinterpret_cast<const float4*>(wr + h);
            acc += shid[h] * wv.x + shid[h + 1] * wv.y + shid[h + 2] * wv.z + shid[h + 3] * wv.w;
        }
        sv[idx] = acc;
    }
    __syncthreads();

    // softmax over groups of 3
    if (tid < 128) {
        const float v0 = sv[tid * 3], v1 = sv[tid * 3 + 1], v2 = sv[tid * 3 + 2];
        const float m = fmaxf(v0, fmaxf(v1, v2));
        const float e0 = expf(v0 - m), e1 = expf(v1 - m), e2 = expf(v2 - m);
        const float s = e0 + e1 + e2;
        g_a[n * 384 + tid * 3 + 0] = e0 / s;
        g_a[n * 384 + tid * 3 + 1] = e1 / s;
        g_a[n * 384 + tid * 3 + 2] = e2 / s;
    }
}

// ---------------------------------------------------------------------------
extern "C" void kernel_launch(void* const* d_in, const int* in_sizes, int n_in,
                              void* d_out, int out_size)
{
    const float* x      = (const float*)d_in[0];
    const float* mlp_w  = (const float*)d_in[1];
    const float* mlp_b  = (const float*)d_in[2];
    const float* bn1_g  = (const float*)d_in[3];
    const float* bn1_b  = (const float*)d_in[4];
    const float* bn1_m  = (const float*)d_in[5];
    const float* bn1_v  = (const float*)d_in[6];
    const float* pos_h  = (const float*)d_in[7];
    const float* pos_w  = (const float*)d_in[8];
    const float* pjh_w  = (const float*)d_in[9];
    const float* pjh_b  = (const float*)d_in[10];
    const float* pjw_w  = (const float*)d_in[11];
    const float* pjw_b  = (const float*)d_in[12];
    const float* fuse_h = (const float*)d_in[13];
    const float* bn2_g  = (const float*)d_in[14];
    const float* bn2_b  = (const float*)d_in[15];
    const float* bn2_m  = (const float*)d_in[16];
    const float* bn2_v  = (const float*)d_in[17];
    const float* fuse_w = (const float*)d_in[18];
    const float* fch_w  = (const float*)d_in[19];
    const float* fcw_w  = (const float*)d_in[20];
    const float* rw_w1  = (const float*)d_in[21];
    const float* rw_b1  = (const float*)d_in[22];
    const float* rw_w2  = (const float*)d_in[23];
    const float* rw_b2  = (const float*)d_in[24];
    const float* fout_w = (const float*)d_in[25];

    float *ap;
    void *ybh, *ybl, *cbh, *cbl, *u1h, *u1l, *x2hp, *x2wp, *wfp;
    cudaGetSymbolAddress((void**)&ap, g_a);
    cudaGetSymbolAddress(&ybh, g_ybh4);
    cudaGetSymbolAddress(&ybl, g_ybl4);
    cudaGetSymbolAddress(&cbh, g_cbh4);
    cudaGetSymbolAddress(&cbl, g_cbl4);
    cudaGetSymbolAddress(&u1h, g_u1h4);
    cudaGetSymbolAddress(&u1l, g_u1l4);
    cudaGetSymbolAddress(&x2hp, g_x2h4);
    cudaGetSymbolAddress(&x2wp, g_x2w4);
    cudaGetSymbolAddress(&wfp, g_wf4);

    const __half* WF = (const __half*)wfp;

    cudaFuncSetAttribute(tc_gemm<1,1,2>, cudaFuncAttributeMaxDynamicSharedMemorySize, SMEM_GEMM);
    cudaFuncSetAttribute(tc_gemm<2,0,0>, cudaFuncAttributeMaxDynamicSharedMemorySize, SMEM_GEMM);
    cudaFuncSetAttribute(tc_g23, cudaFuncAttributeMaxDynamicSharedMemorySize, SMEM_G23);

    wprep_k<<<dim3(6, 8), 256>>>(mlp_w, fuse_h, fuse_w, fout_w);

    // GEMM1: y = gelu(bn(x@mlp_w + b)), ch<128 += pos_h ; fp16 hi/lo out
    tc_gemm<1,1,2><<<dim3(2, NPB), 256, SMEM_GEMM>>>(
        WF, nullptr, nullptr, 0, nullptr, nullptr, 0,
        x, SF, nullptr, 0,
        (__half*)ybh, (__half*)ybl, SF,
        mlp_b, bn1_g, bn1_b, bn1_m, bn1_v, pos_h, nullptr, nullptr, nullptr);

    // merged strips + depthwise
    sd_k<<<dim3(256, 16), 224>>>(pjh_w, pjh_b, pjw_w, pjw_b, fch_w, fcw_w,
        (const __half*)ybh, (const __half*)ybl);
    att_k<<<16, 256>>>(rw_w1, rw_b1, rw_w2, rw_b2);

    // Fused GEMM2+3 -> u1 (fp16 hi/lo)
    tc_g23<<<dim3(1, NPB), 256, SMEM_G23>>>(
        WF + 2L * 40960, WF + 3L * 40960,
        (const __half*)cbh, (const __half*)cbl,
        (const __half*)ybh, (const __half*)ybl,
        (__half*)u1h, (__half*)u1l,
        bn2_g, bn2_b, bn2_m, bn2_v, pos_w);

    // GEMM4 (2-term): out = concat[u1, a0*x2h + a1*x2w + a2*y2]@fuse_out
    tc_gemm<2,0,0><<<dim3(2, NPB), 256, SMEM_GEMM>>>(
        WF + 4L * 40960,
        (const __half*)u1h, (const __half*)u1l, SH,
        (const __half*)ybh + 128L * HWc, (const __half*)ybl + 128L * HWc, SF,
        nullptr, 0, (float*)d_out, SF,
        nullptr, nullptr, 0,
        nullptr, nullptr, nullptr, nullptr, nullptr, nullptr,
        (const __half*)x2hp, (const __half*)x2wp, ap);
}

// round 16
// speedup vs baseline: 1.1349x; 1.0259x over previous
#include <cuda_runtime.h>
#include <cuda_fp16.h>
#include <math.h>
#include <stdint.h>

#define Nn   16
#define Cc   256
#define C1c  128
#define HWc  3136
#define EPSf 1e-5f
#define PBI  25
#define NPB  (Nn*PBI)
#define SF   (Cc*HWc)
#define SH   (C1c*HWc)

// ---------------- scratch (device globals; no allocations) ----------------
__device__ float g_att[Nn*C1c];
__device__ float g_a  [Nn*C1c*3];

__device__ uint4 g_ybh4[(Nn*Cc *HWc + 256) / 8];
__device__ uint4 g_ybl4[(Nn*Cc *HWc + 256) / 8];
__device__ uint4 g_cbh4[(Nn*C1c*HWc + 256) / 8];
__device__ uint4 g_cbl4[(Nn*C1c*HWc + 256) / 8];
__device__ uint4 g_u1h4[(Nn*C1c*HWc + 256) / 8];
__device__ uint4 g_u1l4[(Nn*C1c*HWc + 256) / 8];
__device__ uint4 g_x2h4[(Nn*C1c*HWc + 256) / 8];
__device__ uint4 g_x2w4[(Nn*C1c*HWc + 256) / 8];
// prepped weights (fp16): 6 slots x 8 chunks x [128 n][40 halves]
__device__ uint4 g_wf4[6 * 40960 / 8];

__device__ __forceinline__ float gelu_f(float x) {
    return 0.5f * x * (1.0f + erff(x * 0.7071067811865476f));
}
__device__ __forceinline__ uint32_t smem_to_u32(const void* p) {
    uint32_t a;
    asm("{ .reg .u64 t; cvta.to.shared.u64 t, %1; cvt.u32.u64 %0, t; }" : "=r"(a) : "l"(p));
    return a;
}
__device__ __forceinline__ void split_fp2(float x0, float x1, uint32_t& hi, uint32_t& lo) {
    const __half h0 = __float2half_rn(x0);
    const __half h1 = __float2half_rn(x1);
    const __half l0 = __float2half_rn(x0 - __half2float(h0));
    const __half l1 = __float2half_rn(x1 - __half2float(h1));
    hi = (uint32_t)__half_as_ushort(h0) | ((uint32_t)__half_as_ushort(h1) << 16);
    lo = (uint32_t)__half_as_ushort(l0) | ((uint32_t)__half_as_ushort(l1) << 16);
}
__device__ __forceinline__ uint32_t pack_fp2(float x0, float x1) {
    const __half h0 = __float2half_rn(x0);
    const __half h1 = __float2half_rn(x1);
    return (uint32_t)__half_as_ushort(h0) | ((uint32_t)__half_as_ushort(h1) << 16);
}
__device__ __forceinline__ void ldsm4(uint32_t (&r)[4], uint32_t addr) {
    asm volatile("ldmatrix.sync.aligned.m8n8.x4.shared.b16 {%0,%1,%2,%3}, [%4];"
        : "=r"(r[0]), "=r"(r[1]), "=r"(r[2]), "=r"(r[3]) : "r"(addr));
}
__device__ __forceinline__ void ldsm4t(uint32_t (&r)[4], uint32_t addr) {
    asm volatile("ldmatrix.sync.aligned.m8n8.x4.trans.shared.b16 {%0,%1,%2,%3}, [%4];"
        : "=r"(r[0]), "=r"(r[1]), "=r"(r[2]), "=r"(r[3]) : "r"(addr));
}
__device__ __forceinline__ void mma16816(float (&c)[4], const uint32_t (&a)[4], uint32_t b0, uint32_t b1) {
    asm volatile("mma.sync.aligned.m16n8k16.row.col.f32.f16.f16.f32 "
        "{%0,%1,%2,%3}, {%4,%5,%6,%7}, {%8,%9}, {%0,%1,%2,%3};"
        : "+f"(c[0]), "+f"(c[1]), "+f"(c[2]), "+f"(c[3])
        : "r"(a[0]), "r"(a[1]), "r"(a[2]), "r"(a[3]), "r"(b0), "r"(b1));
}
#define CP16(dst, src) asm volatile("cp.async.cg.shared.global [%0], [%1], 16;" :: "r"(dst), "l"(src))
#define CP_COMMIT()    asm volatile("cp.async.commit_group;" ::: "memory")

// ---------------------------------------------------------------------------
// Weight prep (unchanged).
// ---------------------------------------------------------------------------
__global__ __launch_bounds__(256)
void wprep_k(const float* __restrict__ mlp_w, const float* __restrict__ fuse_h,
             const float* __restrict__ fuse_w, const float* __restrict__ fout_w)
{
    const int slot = blockIdx.x, kc = blockIdx.y, tid = threadIdx.x;
    const float* W; int o0;
    switch (slot) {
        case 0: W = mlp_w;  o0 = 0;   break;
        case 1: W = mlp_w;  o0 = 128; break;
        case 2: W = fuse_h; o0 = 0;   break;
        case 3: W = fuse_w; o0 = 0;   break;
        case 4: W = fout_w; o0 = 0;   break;
        default:W = fout_w; o0 = 128; break;
    }
    const int n = tid >> 1;
    const int kh = (tid & 1) * 16;
    const float* src = W + (long)(o0 + n) * 256 + kc * 32 + kh;
    uint32_t hp[8];
#pragma unroll
    for (int j = 0; j < 8; j++) {
        const float2 v = *reinterpret_cast<const float2*>(src + 2 * j);
        hp[j] = pack_fp2(v.x, v.y);
    }
    __half* dh = (__half*)g_wf4 + (long)slot * 40960 + kc * 5120 + n * 40 + kh;
    *reinterpret_cast<uint4*>(dh)     = *reinterpret_cast<uint4*>(&hp[0]);
    *reinterpret_cast<uint4*>(dh + 8) = *reinterpret_cast<uint4*>(&hp[4]);
    if (tid < 128) {
        const uint4 z = {0, 0, 0, 0};
        *reinterpret_cast<uint4*>((__half*)g_wf4 + (long)slot * 40960 + kc * 5120 + tid * 40 + 32) = z;
    }
}

// ---------------------------------------------------------------------------
// Generic GEMM (exact R12/R14 geometry).
// ---------------------------------------------------------------------------
#define STG 27648
#define ALB 8704
#define BHB 17408
#define SMEM_GEMM 67584

template<int APATH, int EPI, int OUT>
__global__ __launch_bounds__(256, 2)
void tc_gemm(const __half* __restrict__ wf,
             const __half* __restrict__ s1h, const __half* __restrict__ s1l, int str1,
             const __half* __restrict__ s2h, const __half* __restrict__ s2l, int str2,
             const float* __restrict__ xin, int strX,
             float* __restrict__ out, int strO,
             __half* __restrict__ obh, __half* __restrict__ obl, int strOB,
             const float* __restrict__ e_bias,
             const float* __restrict__ e_g, const float* __restrict__ e_b,
             const float* __restrict__ e_m, const float* __restrict__ e_v,
             const float* __restrict__ e_pos,
             const __half* __restrict__ cH, const __half* __restrict__ cW,
             const float* __restrict__ cA)
{
    extern __shared__ __align__(16) char smc[];
    const uint32_t sm_sa = smem_to_u32(smc);

    const int tid = threadIdx.x;
    const int wid = tid >> 5;
    const int lane = tid & 31;
    const int o0 = blockIdx.x * 128;
    const int nimg = blockIdx.y / PBI;
    const int pix0 = (blockIdx.y % PBI) * 128;
    const int warp_m = (wid & 3) * 32;
    const int warp_n = (wid >> 2) * 64;

    const __half* wfB = wf + (long)blockIdx.x * 40960;

    const int pix2 = tid & 63;
    const int rgrp = tid >> 6;
    int p0 = pix0 + 2 * pix2;
    if (p0 > HWc - 2) p0 = HWc - 2;

    auto issue = [&](int kc, int buf) {
        const uint32_t base = sm_sa + buf * STG;
        char* bp = smc + buf * STG;
        if (APATH == 1) {
            const float* src = xin + (long)nimg * strX + p0;
#pragma unroll
            for (int j = 0; j < 8; j++) {
                const int r = rgrp + 4 * j;
                const float2 v = *reinterpret_cast<const float2*>(src + (long)(kc * 32 + r) * HWc);
                uint32_t hi, lo;
                split_fp2(v.x, v.y, hi, lo);
                *reinterpret_cast<uint32_t*>(bp + r * 272 + pix2 * 4) = hi;
                *reinterpret_cast<uint32_t*>(bp + ALB + r * 272 + pix2 * 4) = lo;
            }
        } else if (kc < 4) {
            const long chb = (long)nimg * str1 + (long)(kc * 32) * HWc + pix0;
#pragma unroll
            for (int it = 0; it < 2; it++) {
                const int idx = tid + it * 256;
                const int row = idx >> 4, seg = idx & 15;
                const char* gh = (const char*)(s1h + chb + (long)row * HWc) + seg * 16;
                const char* gl = (const char*)(s1l + chb + (long)row * HWc) + seg * 16;
                CP16(base + row * 272 + seg * 16, gh);
                CP16(base + ALB + row * 272 + seg * 16, gl);
            }
        } else {
            const long ib = (long)nimg * SH + p0;
            const __half* pH = cH + ib;
            const __half* pW = cW + ib;
            const __half* pXh = s2h + (long)nimg * str2 + p0;
            const __half* pXl = s2l + (long)nimg * str2 + p0;
            const float* aB = cA + nimg * 384;
#pragma unroll
            for (int j = 0; j < 8; j++) {
                const int r = rgrp + 4 * j;
                const int cc = (kc - 4) * 32 + r;
                const float a0 = aB[cc * 3], a1 = aB[cc * 3 + 1], a2 = aB[cc * 3 + 2];
                const __half2 vh2 = *reinterpret_cast<const __half2*>(pH + (long)cc * HWc);
                const __half2 vw2 = *reinterpret_cast<const __half2*>(pW + (long)cc * HWc);
                const __half2 xh2 = *reinterpret_cast<const __half2*>(pXh + (long)cc * HWc);
                const __half2 xl2 = *reinterpret_cast<const __half2*>(pXl + (long)cc * HWc);
                float2 v;
                v.x = a0 * __half2float(vh2.x) + a1 * __half2float(vw2.x)
                    + a2 * (__half2float(xh2.x) + __half2float(xl2.x));
                v.y = a0 * __half2float(vh2.y) + a1 * __half2float(vw2.y)
                    + a2 * (__half2float(xh2.y) + __half2float(xl2.y));
                uint32_t hi, lo;
                split_fp2(v.x, v.y, hi, lo);
                *reinterpret_cast<uint32_t*>(bp + r * 272 + pix2 * 4) = hi;
                *reinterpret_cast<uint32_t*>(bp + ALB + r * 272 + pix2 * 4) = lo;
            }
        }
        const char* wsrc = (const char*)(wfB + kc * 5120);
#pragma unroll
        for (int it = 0; it < 3; it++) {
            const int i = tid + it * 256;
            if (i < 640) CP16(base + BHB + i * 16, wsrc + i * 16);
        }
    };

    const int a_kr = (lane & 7) + ((lane & 16) >> 1);
    const int a_mc = (lane & 8);
    const int b_nr = (lane & 7) + ((lane & 16) >> 1);
    const int b_kc = (lane & 8);

    float acc[2][8][4];
#pragma unroll
    for (int mt = 0; mt < 2; mt++)
#pragma unroll
        for (int nf = 0; nf < 8; nf++)
#pragma unroll
            for (int j = 0; j < 4; j++) acc[mt][nf][j] = 0.f;

    issue(0, 0);
    CP_COMMIT();

#pragma unroll 1
    for (int kc = 0; kc < 8; kc++) {
        if (kc < 7) { issue(kc + 1, (kc + 1) & 1); CP_COMMIT(); }
        if (kc < 7) asm volatile("cp.async.wait_group 1;" ::: "memory");
        else        asm volatile("cp.async.wait_group 0;" ::: "memory");
        __syncthreads();

        const uint32_t base = sm_sa + (kc & 1) * STG;
#pragma unroll
        for (int ks = 0; ks < 2; ks++) {
            const int k0 = ks * 16;
            uint32_t ah[2][4], al[2][4];
#pragma unroll
            for (int half = 0; half < 2; half++) {
                const uint32_t ea = (uint32_t)((k0 + a_kr) * 136 + warp_m + half * 16 + a_mc) * 2;
                ldsm4t(ah[half], base + ea);
                ldsm4t(al[half], base + ALB + ea);
            }
#pragma unroll
            for (int ng = 0; ng < 4; ng++) {
                const uint32_t eb = (uint32_t)((warp_n + ng * 16 + b_nr) * 40 + k0 + b_kc) * 2;
                uint32_t th[4];
                ldsm4(th, base + BHB + eb);
#pragma unroll
                for (int mt = 0; mt < 2; mt++) {
                    mma16816(acc[mt][2 * ng],     ah[mt], th[0], th[1]);
                    mma16816(acc[mt][2 * ng],     al[mt], th[0], th[1]);
                    mma16816(acc[mt][2 * ng + 1], ah[mt], th[2], th[3]);
                    mma16816(acc[mt][2 * ng + 1], al[mt], th[2], th[3]);
                }
            }
        }
        __syncthreads();
    }

    // ---- epilogue ----
    float* O = reinterpret_cast<float*>(smc);
#pragma unroll
    for (int mt = 0; mt < 2; mt++)
#pragma unroll
        for (int nf = 0; nf < 8; nf++) {
            const int n = warp_n + nf * 8 + (lane & 3) * 2;
            const int m = warp_m + mt * 16 + (lane >> 2);
            O[n * 132 + m]           = acc[mt][nf][0];
            O[(n + 1) * 132 + m]     = acc[mt][nf][1];
            O[n * 132 + m + 8]       = acc[mt][nf][2];
            O[(n + 1) * 132 + m + 8] = acc[mt][nf][3];
        }
    __syncthreads();

    {
        const int m0 = lane * 4;
        const int hw0 = pix0 + m0;
        const bool pvalid = (hw0 < HWc);
        int rel[4] = {0, 0, 0, 0};
        if (pvalid && EPI != 0) {
#pragma unroll
            for (int j = 0; j < 4; j++) {
                const int hwj = hw0 + j;
                const int h = hwj / 56;
                rel[j] = (hwj - h * 56) - h + 56;
            }
        }
        if (pvalid) {
#pragma unroll
            for (int r = 0; r < 16; r++) {
                const int n = wid * 16 + r;
                const int o = o0 + n;
                const float4 v = *reinterpret_cast<const float4*>(&O[n * 132 + m0]);
                float vv[4] = {v.x, v.y, v.z, v.w};
                if (EPI == 1) {
                    const float s = __ldg(&e_g[o]) * rsqrtf(__ldg(&e_v[o]) + EPSf);
                    const float t = __ldg(&e_b[o]) - __ldg(&e_m[o]) * s;
                    const float bb = __ldg(&e_bias[o]);
#pragma unroll
                    for (int j = 0; j < 4; j++) {
                        float u = gelu_f((vv[j] + bb) * s + t);
                        if (o < 128) u += __ldg(&e_pos[rel[j] * 128 + o]);
                        vv[j] = u;
                    }
                }
                if (OUT != 2) {
                    float4 ov;
                    ov.x = vv[0]; ov.y = vv[1]; ov.z = vv[2]; ov.w = vv[3];
                    *reinterpret_cast<float4*>(&out[(long)nimg * strO + (long)o * HWc + hw0]) = ov;
                }
                if (OUT != 0) {
                    uint32_t h0, l0, h1, l1;
                    split_fp2(vv[0], vv[1], h0, l0);
                    split_fp2(vv[2], vv[3], h1, l1);
                    const long eoff = (long)nimg * strOB + (long)o * HWc + hw0;
                    *reinterpret_cast<uint2*>(obh + eoff) = make_uint2(h0, h1);
                    *reinterpret_cast<uint2*>(obl + eoff) = make_uint2(l0, l1);
                }
            }
        }
    }
}

// ---------------------------------------------------------------------------
// Fused GEMM2+GEMM3 with attention-MLP rider blocks (blockIdx.y >= NPB).
// ---------------------------------------------------------------------------
#define T_OFF 55296
#define SMEM_G23 90112

__global__ __launch_bounds__(256, 2)
void tc_g23(const __half* __restrict__ wf2, const __half* __restrict__ wf3,
            const __half* __restrict__ s1h, const __half* __restrict__ s1l,
            const __half* __restrict__ yh, const __half* __restrict__ yl,
            __half* __restrict__ obh, __half* __restrict__ obl,
            const float* __restrict__ e_g, const float* __restrict__ e_b,
            const float* __restrict__ e_m, const float* __restrict__ e_v,
            const float* __restrict__ e_pos,
            const float* __restrict__ aw1, const float* __restrict__ ab1,
            const float* __restrict__ aw2, const float* __restrict__ ab2)
{
    extern __shared__ __align__(16) char smc[];
    const uint32_t sm_sa = smem_to_u32(smc);

    const int tid = threadIdx.x;

    // ================= attention-MLP rider blocks =================
    if (blockIdx.y >= NPB) {
        float* satt = reinterpret_cast<float*>(smc);          // 128
        float* shid = reinterpret_cast<float*>(smc) + 128;    // 64
        float* sv   = reinterpret_cast<float*>(smc) + 192;    // 384
        const int n = blockIdx.y - NPB;

        if (tid < 128) satt[tid] = g_att[n * 128 + tid];
        __syncthreads();
        {
            const int o = tid >> 2;
            const int part = tid & 3;
            const float* wr = aw1 + o * 128 + part * 32;
            const float* sa = satt + part * 32;
            float acc = 0.f;
#pragma unroll
            for (int c = 0; c < 32; c += 4) {
                const float4 wv = *reinterpret_cast<const float4*>(wr + c);
                acc += sa[c] * wv.x + sa[c + 1] * wv.y + sa[c + 2] * wv.z + sa[c + 3] * wv.w;
            }
            acc += __shfl_xor_sync(0xffffffffu, acc, 1);
            acc += __shfl_xor_sync(0xffffffffu, acc, 2);
            if (part == 0) shid[o] = gelu_f(acc + __ldg(&ab1[o]));
        }
        __syncthreads();
        for (int idx = tid; idx < 384; idx += 256) {
            const float* wr = aw2 + idx * 64;
            float acc = __ldg(&ab2[idx]);
#pragma unroll
            for (int h = 0; h < 64; h += 4) {
                const float4 wv = *reinterpret_cast<const float4*>(wr + h);
                acc += shid[h] * wv.x + shid[h + 1] * wv.y + shid[h + 2] * wv.z + shid[h + 3] * wv.w;
            }
            sv[idx] = acc;
        }
        __syncthreads();
        if (tid < 128) {
            const float v0 = sv[tid * 3], v1 = sv[tid * 3 + 1], v2 = sv[tid * 3 + 2];
            const float m = fmaxf(v0, fmaxf(v1, v2));
            const float e0 = expf(v0 - m), e1 = expf(v1 - m), e2 = expf(v2 - m);
            const float s = e0 + e1 + e2;
            g_a[n * 384 + tid * 3 + 0] = e0 / s;
            g_a[n * 384 + tid * 3 + 1] = e1 / s;
            g_a[n * 384 + tid * 3 + 2] = e2 / s;
        }
        return;
    }

    // ================= fused GEMM2+GEMM3 =================
    const int wid = tid >> 5;
    const int lane = tid & 31;
    const int nimg = blockIdx.y / PBI;
    const int pix0 = (blockIdx.y % PBI) * 128;
    const int warp_m = (wid & 3) * 32;
    const int warp_n = (wid >> 2) * 64;

    const int a_kr = (lane & 7) + ((lane & 16) >> 1);
    const int a_mc = (lane & 8);
    const int b_nr = (lane & 7) + ((lane & 16) >> 1);
    const int b_kc = (lane & 8);

    auto stageA = [&](const __half* sh, const __half* sl, int str, int c0, uint32_t base) {
        const long chb = (long)nimg * str + (long)c0 * HWc + pix0;
#pragma unroll
        for (int it = 0; it < 2; it++) {
            const int idx = tid + it * 256;
            const int row = idx >> 4, seg = idx & 15;
            const char* gh = (const char*)(sh + chb + (long)row * HWc) + seg * 16;
            const char* gl = (const char*)(sl + chb + (long)row * HWc) + seg * 16;
            CP16(base + row * 272 + seg * 16, gh);
            CP16(base + ALB + row * 272 + seg * 16, gl);
        }
    };
    auto stageB = [&](const __half* wf, int kc, uint32_t base) {
        const char* wsrc = (const char*)(wf + kc * 5120);
#pragma unroll
        for (int it = 0; it < 3; it++) {
            const int i = tid + it * 256;
            if (i < 640) CP16(base + BHB + i * 16, wsrc + i * 16);
        }
    };

    float acc[2][8][4];
#pragma unroll
    for (int mt = 0; mt < 2; mt++)
#pragma unroll
        for (int nf = 0; nf < 8; nf++)
#pragma unroll
            for (int j = 0; j < 4; j++) acc[mt][nf][j] = 0.f;

    auto issue1 = [&](int kc, int buf) {
        const uint32_t base = sm_sa + buf * STG;
        if (kc < 4) stageA(s1h, s1l, SH, kc * 32, base);
        else        stageA(yh,  yl,  SF, (kc - 4) * 32, base);
        stageB(wf2, kc, base);
    };

    issue1(0, 0);
    CP_COMMIT();

#pragma unroll 1
    for (int kc = 0; kc < 8; kc++) {
        if (kc < 7) { issue1(kc + 1, (kc + 1) & 1); CP_COMMIT(); }
        if (kc < 7) asm volatile("cp.async.wait_group 1;" ::: "memory");
        else        asm volatile("cp.async.wait_group 0;" ::: "memory");
        __syncthreads();

        const uint32_t base = sm_sa + (kc & 1) * STG;
#pragma unroll
        for (int ks = 0; ks < 2; ks++) {
            const int k0 = ks * 16;
            uint32_t ah[2][4], al[2][4];
#pragma unroll
            for (int half = 0; half < 2; half++) {
                const uint32_t ea = (uint32_t)((k0 + a_kr) * 136 + warp_m + half * 16 + a_mc) * 2;
                ldsm4t(ah[half], base + ea);
                ldsm4t(al[half], base + ALB + ea);
            }
#pragma unroll
            for (int ng = 0; ng < 4; ng++) {
                const uint32_t eb = (uint32_t)((warp_n + ng * 16 + b_nr) * 40 + k0 + b_kc) * 2;
                uint32_t th[4];
                ldsm4(th, base + BHB + eb);
#pragma unroll
                for (int mt = 0; mt < 2; mt++) {
                    mma16816(acc[mt][2 * ng],     ah[mt], th[0], th[1]);
                    mma16816(acc[mt][2 * ng],     al[mt], th[0], th[1]);
                    mma16816(acc[mt][2 * ng + 1], ah[mt], th[2], th[3]);
                    mma16816(acc[mt][2 * ng + 1], al[mt], th[2], th[3]);
                }
            }
        }
        __syncthreads();
    }

    stageB(wf3, 0, sm_sa);
    CP_COMMIT();

    {
        __half* T = reinterpret_cast<__half*>(smc + T_OFF);
#pragma unroll
        for (int nf = 0; nf < 8; nf++) {
            const int n0 = warp_n + nf * 8 + (lane & 3) * 2;
            const float sA = __ldg(&e_g[n0]) * rsqrtf(__ldg(&e_v[n0]) + EPSf);
            const float tA = __ldg(&e_b[n0]) - __ldg(&e_m[n0]) * sA;
            const float sB = __ldg(&e_g[n0 + 1]) * rsqrtf(__ldg(&e_v[n0 + 1]) + EPSf);
            const float tB = __ldg(&e_b[n0 + 1]) - __ldg(&e_m[n0 + 1]) * sB;
#pragma unroll
            for (int mt = 0; mt < 2; mt++) {
                const int m = warp_m + mt * 16 + (lane >> 2);
                int hw = pix0 + m; if (hw > HWc - 1) hw = HWc - 1;
                int h = hw / 56;
                const int rel0 = (hw - h * 56) - h + 56;
                int hw8 = pix0 + m + 8; if (hw8 > HWc - 1) hw8 = HWc - 1;
                h = hw8 / 56;
                const int rel8 = (hw8 - h * 56) - h + 56;
                const float v0 = gelu_f(acc[mt][nf][0] * sA + tA) + __ldg(&e_pos[rel0 * 128 + n0]);
                const float v1 = gelu_f(acc[mt][nf][1] * sB + tB) + __ldg(&e_pos[rel0 * 128 + n0 + 1]);
                const float v2 = gelu_f(acc[mt][nf][2] * sA + tA) + __ldg(&e_pos[rel8 * 128 + n0]);
                const float v3 = gelu_f(acc[mt][nf][3] * sB + tB) + __ldg(&e_pos[rel8 * 128 + n0 + 1]);
                T[n0 * 136 + m]            = __float2half_rn(v0);
                T[(n0 + 1) * 136 + m]      = __float2half_rn(v1);
                T[n0 * 136 + m + 8]        = __float2half_rn(v2);
                T[(n0 + 1) * 136 + m + 8]  = __float2half_rn(v3);
            }
        }
    }
    __syncthreads();

#pragma unroll
    for (int mt = 0; mt < 2; mt++)
#pragma unroll
        for (int nf = 0; nf < 8; nf++)
#pragma unroll
            for (int j = 0; j < 4; j++) acc[mt][nf][j] = 0.f;

    auto issue2 = [&](int kc, int buf) {
        const uint32_t base = sm_sa + buf * STG;
        if (kc >= 4) stageA(yh + 128L * HWc, yl + 128L * HWc, SF, (kc - 4) * 32, base);
        stageB(wf3, kc, base);
    };

#pragma unroll 1
    for (int kc = 0; kc < 8; kc++) {
        if (kc < 7) { issue2(kc + 1, (kc + 1) & 1); CP_COMMIT(); }
        if (kc < 7) asm volatile("cp.async.wait_group 1;" ::: "memory");
        else        asm volatile("cp.async.wait_group 0;" ::: "memory");
        __syncthreads();

        const uint32_t base = sm_sa + (kc & 1) * STG;
        if (kc < 4) {
#pragma unroll
            for (int ks = 0; ks < 2; ks++) {
                const int k0 = ks * 16;
                uint32_t ah[2][4];
#pragma unroll
                for (int half = 0; half < 2; half++) {
                    const uint32_t ea = (uint32_t)((kc * 32 + k0 + a_kr) * 136 + warp_m + half * 16 + a_mc) * 2;
                    ldsm4t(ah[half], sm_sa + T_OFF + ea);
                }
#pragma unroll
                for (int ng = 0; ng < 4; ng++) {
                    const uint32_t eb = (uint32_t)((warp_n + ng * 16 + b_nr) * 40 + k0 + b_kc) * 2;
                    uint32_t th[4];
                    ldsm4(th, base + BHB + eb);
#pragma unroll
                    for (int mt = 0; mt < 2; mt++) {
                        mma16816(acc[mt][2 * ng],     ah[mt], th[0], th[1]);
                        mma16816(acc[mt][2 * ng + 1], ah[mt], th[2], th[3]);
                    }
                }
            }
        } else {
#pragma unroll
            for (int ks = 0; ks < 2; ks++) {
                const int k0 = ks * 16;
                uint32_t ah[2][4], al[2][4];
#pragma unroll
                for (int half = 0; half < 2; half++) {
                    const uint32_t ea = (uint32_t)((k0 + a_kr) * 136 + warp_m + half * 16 + a_mc) * 2;
                    ldsm4t(ah[half], base + ea);
                    ldsm4t(al[half], base + ALB + ea);
                }
#pragma unroll
                for (int ng = 0; ng < 4; ng++) {
                    const uint32_t eb = (uint32_t)((warp_n + ng * 16 + b_nr) * 40 + k0 + b_kc) * 2;
                    uint32_t th[4];
                    ldsm4(th, base + BHB + eb);
#pragma unroll
                    for (int mt = 0; mt < 2; mt++) {
                        mma16816(acc[mt][2 * ng],     ah[mt], th[0], th[1]);
                        mma16816(acc[mt][2 * ng],     al[mt], th[0], th[1]);
                        mma16816(acc[mt][2 * ng + 1], ah[mt], th[2], th[3]);
                        mma16816(acc[mt][2 * ng + 1], al[mt], th[2], th[3]);
                    }
                }
            }
        }
        __syncthreads();
    }

    float* O = reinterpret_cast<float*>(smc);
#pragma unroll
    for (int mt = 0; mt < 2; mt++)
#pragma unroll
        for (int nf = 0; nf < 8; nf++) {
            const int n = warp_n + nf * 8 + (lane & 3) * 2;
            const int m = warp_m + mt * 16 + (lane >> 2);
            O[n * 132 + m]           = acc[mt][nf][0];
            O[(n + 1) * 132 + m]     = acc[mt][nf][1];
            O[n * 132 + m + 8]       = acc[mt][nf][2];
            O[(n + 1) * 132 + m + 8] = acc[mt][nf][3];
        }
    __syncthreads();

    {
        const int m0 = lane * 4;
        const int hw0 = pix0 + m0;
        if (hw0 < HWc) {
#pragma unroll
            for (int r = 0; r < 16; r++) {
                const int n = wid * 16 + r;
                const float4 v = *reinterpret_cast<const float4*>(&O[n * 132 + m0]);
                uint32_t h0, l0, h1, l1;
                split_fp2(v.x, v.y, h0, l0);
                split_fp2(v.z, v.w, h1, l1);
                const long eoff = (long)nimg * SH + (long)n * HWc + hw0;
                *reinterpret_cast<uint2*>(obh + eoff) = make_uint2(h0, h1);
                *reinterpret_cast<uint2*>(obl + eoff) = make_uint2(l0, l1);
            }
        }
    }
}

// ---------------------------------------------------------------------------
// Merged strip + depthwise kernel (unchanged from R14/R15).
// ---------------------------------------------------------------------------
__global__ __launch_bounds__(224)
void sd_k(const float* __restrict__ Wh, const float* __restrict__ bh,
          const float* __restrict__ Ww, const float* __restrict__ bw,
          const float* __restrict__ dwh, const float* __restrict__ dww,
          const __half* __restrict__ yh, const __half* __restrict__ yl)
{
    __shared__ float sm[6500];
    const int n = blockIdx.y;
    const int tid = threadIdx.x;

    if (blockIdx.x < 128) {
        float* xs = sm;
        float* os = sm + 3364;
        const bool WVAR = blockIdx.x >= 64;
        const int c = blockIdx.x & 63;
        const float* Wg = WVAR ? Ww : Wh;
        const float* bias = WVAR ? bw : bh;

        for (int i = tid; i < 3364; i += 224) xs[i] = 0.f;
        __syncthreads();
        {
            const long yb = (long)n * SF + (long)((WVAR ? 64 : 0) + c) * HWc;
            for (int i = tid; i < HWc; i += 224) {
                const float v = __half2float(yh[yb + i]) + __half2float(yl[yb + i]);
                const int h = i / 56, w = i - h * 56;
                if (WVAR) xs[(1 + w) * 58 + 1 + h] = v;
                else      xs[(1 + h) * 58 + 1 + w] = v;
            }
        }
        __syncthreads();

        const int oo = tid >> 2;
        const int base0 = (tid & 3) * 14;
        const float* wrow = Wg + ((long)c * 56 + oo) * 168;

        float acc[14];
        const float bval = __ldg(&bias[c * 56 + oo]);
#pragma unroll
        for (int i = 0; i < 14; i++) acc[i] = bval;

        for (int hp = 0; hp < 56; hp++) {
            const float w0 = __ldg(&wrow[hp * 3 + 0]);
            const float w1 = __ldg(&wrow[hp * 3 + 1]);
            const float w2 = __ldg(&wrow[hp * 3 + 2]);
            const float* xr = xs + (1 + hp) * 58 + base0;
            float xv[16];
#pragma unroll
            for (int t = 0; t < 16; t++) xv[t] = xr[t];
#pragma unroll
            for (int i = 0; i < 14; i++) acc[i] += w0 * xv[i] + w1 * xv[i + 1] + w2 * xv[i + 2];
        }

        __half* cbh = (__half*)g_cbh4;
        __half* cbl = (__half*)g_cbl4;

        if (!WVAR) {
            const long dst = (long)n * SH + (long)c * HWc + oo * 56 + base0;
#pragma unroll
            for (int i = 0; i < 7; i++) {
                uint32_t hi, lo;
                split_fp2(acc[2 * i], acc[2 * i + 1], hi, lo);
                *reinterpret_cast<uint32_t*>(cbh + dst + 2 * i) = hi;
                *reinterpret_cast<uint32_t*>(cbl + dst + 2 * i) = lo;
            }
        } else {
#pragma unroll
            for (int i = 0; i < 14; i++) os[(base0 + i) * 56 + oo] = acc[i];
            __syncthreads();
            const int p0 = tid * 14;
            const long dst = (long)n * SH + (long)(64 + c) * HWc + p0;
#pragma unroll
            for (int i = 0; i < 7; i++) {
                uint32_t hi, lo;
                split_fp2(os[p0 + 2 * i], os[p0 + 2 * i + 1], hi, lo);
                *reinterpret_cast<uint32_t*>(cbh + dst + 2 * i) = hi;
                *reinterpret_cast<uint32_t*>(cbl + dst + 2 * i) = lo;
            }
        }
    } else {
        float* xs = sm;
        float* red = sm + 3844;
        const int c = blockIdx.x - 128;

        for (int i = tid; i < 3844; i += 224) xs[i] = 0.f;
        __syncthreads();
        const long yb = (long)n * SF + (long)(128 + c) * HWc;
        for (int i = tid; i < HWc; i += 224) {
            const int h = i / 56;
            xs[(3 + h) * 62 + 3 + (i - h * 56)] = __half2float(yh[yb + i]) + __half2float(yl[yb + i]);
        }
        __syncthreads();

        float kh_[21], kw_[21];
#pragma unroll
        for (int i = 0; i < 21; i++) { kh_[i] = __ldg(&dwh[c * 21 + i]); kw_[i] = __ldg(&dww[c * 21 + i]); }

        const int w = tid % 56;
        const int r0 = (tid / 56) * 14;

        float R[3][7], V[7][3];
#pragma unroll
        for (int a = 0; a < 3; a++)
#pragma unroll
            for (int b = 0; b < 7; b++) R[a][b] = xs[(2 + r0 + a) * 62 + w + b];
#pragma unroll
        for (int a = 0; a < 7; a++)
#pragma unroll
            for (int b = 0; b < 3; b++) V[a][b] = xs[(r0 + a) * 62 + 2 + w + b];

        float lsum = 0.f;
        __half* dh = (__half*)g_x2h4 + (long)n * SH + (long)c * HWc + w;
        __half* dv = (__half*)g_x2w4 + (long)n * SH + (long)c * HWc + w;

#pragma unroll
        for (int j = 0; j < 14; j++) {
            float vh = 0.f, vw = 0.f;
#pragma unroll
            for (int a = 0; a < 3; a++)
#pragma unroll
                for (int b = 0; b < 7; b++)
                    vh += kh_[a * 7 + b] * R[(j + a) % 3][b];
#pragma unroll
            for (int a = 0; a < 7; a++)
#pragma unroll
                for (int b = 0; b < 3; b++)
                    vw += kw_[a * 3 + b] * V[(j + a) % 7][b];
            const float cen = R[(j + 1) % 3][3];
            dh[(r0 + j) * 56] = __float2half_rn(vh);
            dv[(r0 + j) * 56] = __float2half_rn(vw);
            lsum += vh + vw + cen;
            if (j < 13) {
#pragma unroll
                for (int b = 0; b < 7; b++) R[j % 3][b] = xs[(2 + r0 + j + 3) * 62 + w + b];
#pragma unroll
                for (int b = 0; b < 3; b++) V[j % 7][b] = xs[(r0 + j + 7) * 62 + 2 + w + b];
            }
        }

#pragma unroll
        for (int off = 16; off; off >>= 1) lsum += __shfl_down_sync(0xffffffffu, lsum, off);
        if ((tid & 31) == 0) red[tid >> 5] = lsum;
        __syncthreads();
        if (tid == 0) {
            float s = 0.f;
#pragma unroll
            for (int i = 0; i < 7; i++) s += red[i];
            g_att[n * 128 + c] = s * (1.0f / HWc);
        }
    }
}

// ---------------------------------------------------------------------------
extern "C" void kernel_launch(void* const* d_in, const int* in_sizes, int n_in,
                              void* d_out, int out_size)
{
    const float* x      = (const float*)d_in[0];
    const float* mlp_w  = (const float*)d_in[1];
    const float* mlp_b  = (const float*)d_in[2];
    const float* bn1_g  = (const float*)d_in[3];
    const float* bn1_b  = (const float*)d_in[4];
    const float* bn1_m  = (const float*)d_in[5];
    const float* bn1_v  = (const float*)d_in[6];
    const float* pos_h  = (const float*)d_in[7];
    const float* pos_w  = (const float*)d_in[8];
    const float* pjh_w  = (const float*)d_in[9];
    const float* pjh_b  = (const float*)d_in[10];
    const float* pjw_w  = (const float*)d_in[11];
    const float* pjw_b  = (const float*)d_in[12];
    const float* fuse_h = (const float*)d_in[13];
    const float* bn2_g  = (const float*)d_in[14];
    const float* bn2_b  = (const float*)d_in[15];
    const float* bn2_m  = (const float*)d_in[16];
    const float* bn2_v  = (const float*)d_in[17];
    const float* fuse_w = (const float*)d_in[18];
    const float* fch_w  = (const float*)d_in[19];
    const float* fcw_w  = (const float*)d_in[20];
    const float* rw_w1  = (const float*)d_in[21];
    const float* rw_b1  = (const float*)d_in[22];
    const float* rw_w2  = (const float*)d_in[23];
    const float* rw_b2  = (const float*)d_in[24];
    const float* fout_w = (const float*)d_in[25];

    float *ap;
    void *ybh, *ybl, *cbh, *cbl, *u1h, *u1l, *x2hp, *x2wp, *wfp;
    cudaGetSymbolAddress((void**)&ap, g_a);
    cudaGetSymbolAddress(&ybh, g_ybh4);
    cudaGetSymbolAddress(&ybl, g_ybl4);
    cudaGetSymbolAddress(&cbh, g_cbh4);
    cudaGetSymbolAddress(&cbl, g_cbl4);
    cudaGetSymbolAddress(&u1h, g_u1h4);
    cudaGetSymbolAddress(&u1l, g_u1l4);
    cudaGetSymbolAddress(&x2hp, g_x2h4);
    cudaGetSymbolAddress(&x2wp, g_x2w4);
    cudaGetSymbolAddress(&wfp, g_wf4);

    const __half* WF = (const __half*)wfp;

    cudaFuncSetAttribute(tc_gemm<1,1,2>, cudaFuncAttributeMaxDynamicSharedMemorySize, SMEM_GEMM);
    cudaFuncSetAttribute(tc_gemm<2,0,0>, cudaFuncAttributeMaxDynamicSharedMemorySize, SMEM_GEMM);
    cudaFuncSetAttribute(tc_g23, cudaFuncAttributeMaxDynamicSharedMemorySize, SMEM_G23);

    wprep_k<<<dim3(6, 8), 256>>>(mlp_w, fuse_h, fuse_w, fout_w);

    // GEMM1: y = gelu(bn(x@mlp_w + b)), ch<128 += pos_h ; fp16 hi/lo out
    tc_gemm<1,1,2><<<dim3(2, NPB), 256, SMEM_GEMM>>>(
        WF, nullptr, nullptr, 0, nullptr, nullptr, 0,
        x, SF, nullptr, 0,
        (__half*)ybh, (__half*)ybl, SF,
        mlp_b, bn1_g, bn1_b, bn1_m, bn1_v, pos_h, nullptr, nullptr, nullptr);

    // merged strips + depthwise
    sd_k<<<dim3(256, 16), 224>>>(pjh_w, pjh_b, pjw_w, pjw_b, fch_w, fcw_w,
        (const __half*)ybh, (const __half*)ybl);

    // Fused GEMM2+3 -> u1 (fp16 hi/lo), with att-MLP riding on blocks >= NPB
    tc_g23<<<dim3(1, NPB + 16), 256, SMEM_G23>>>(
        WF + 2L * 40960, WF + 3L * 40960,
        (const __half*)cbh, (const __half*)cbl,
        (const __half*)ybh, (const __half*)ybl,
        (__half*)u1h, (__half*)u1l,
        bn2_g, bn2_b, bn2_m, bn2_v, pos_w,
        rw_w1, rw_b1, rw_w2, rw_b2);

    // GEMM4 (2-term): out = concat[u1, a0*x2h + a1*x2w + a2*y2]@fuse_out
    tc_gemm<2,0,0><<<dim3(2, NPB), 256, SMEM_GEMM>>>(
        WF + 4L * 40960,
        (const __half*)u1h, (const __half*)u1l, SH,
        (const __half*)ybh + 128L * HWc, (const __half*)ybl + 128L * HWc, SF,
        nullptr, 0, (float*)d_out, SF,
        nullptr, nullptr, 0,
        nullptr, nullptr, nullptr, nullptr, nullptr, nullptr,
        (const __half*)x2hp, (const __half*)x2wp, ap);
}